// round 14
// baseline (speedup 1.0000x reference)
#include <cuda_runtime.h>
#include <cuda_fp16.h>
#include <math.h>
#include <stdint.h>

// Problem constants
#define SEQ   4096
#define DM    1024
#define NH    16
#define DH    64

// ---------------- scratch (no allocations allowed) ----------------
// QKV GEMM operands (fp16, 1-pass): x, W (Wq,Wk,Wv stacked rows)
__device__ __half g_x16h[SEQ * DM];
__device__ __half g_w16[3 * DM * DM];
// proj GEMM operands (fp16, 1-pass)
__device__ __half g_w16o[DM * DM];
__device__ __half g_a16h[SEQ * DM];        // attention out (fp16)

// flash operands (fp16), written directly by the QKV epilogue
__device__ __half g_qh[SEQ * DM];   // roped Q, pre-scaled by (1/8)*log2e
__device__ __half g_kh[SEQ * DM];   // roped K
__device__ __half g_vh[SEQ * DM];   // V

// rope table: [s][i*2]=cos, [i*2+1]=sin  (i = 0..31)
__device__ float g_rope[SEQ][64];

// ---------------- low-level helpers ----------------
__device__ __forceinline__ uint32_t smem_u32(const void* p) {
    uint32_t a;
    asm("{ .reg .u64 t; cvta.to.shared.u64 t, %1; cvt.u32.u64 %0, t; }" : "=r"(a) : "l"(p));
    return a;
}
__device__ __forceinline__ void cp_async16(uint32_t sa, const void* ga) {
    asm volatile("cp.async.cg.shared.global [%0], [%1], 16;" :: "r"(sa), "l"(ga));
}
#define CP_COMMIT() asm volatile("cp.async.commit_group;" ::: "memory")
#define CP_WAIT2()  asm volatile("cp.async.wait_group 2;" ::: "memory")
#define CP_WAIT1()  asm volatile("cp.async.wait_group 1;" ::: "memory")
#define CP_WAIT0()  asm volatile("cp.async.wait_group 0;" ::: "memory")

__device__ __forceinline__ void ldsm_x4(uint32_t* r, uint32_t addr) {
    asm volatile("ldmatrix.sync.aligned.m8n8.x4.shared.b16 {%0,%1,%2,%3}, [%4];"
        : "=r"(r[0]), "=r"(r[1]), "=r"(r[2]), "=r"(r[3]) : "r"(addr));
}
__device__ __forceinline__ void ldsm_x4t(uint32_t* r, uint32_t addr) {
    asm volatile("ldmatrix.sync.aligned.m8n8.x4.trans.shared.b16 {%0,%1,%2,%3}, [%4];"
        : "=r"(r[0]), "=r"(r[1]), "=r"(r[2]), "=r"(r[3]) : "r"(addr));
}
__device__ __forceinline__ void ldsm_x2t(uint32_t* r, uint32_t addr) {
    asm volatile("ldmatrix.sync.aligned.m8n8.x2.trans.shared.b16 {%0,%1}, [%2];"
        : "=r"(r[0]), "=r"(r[1]) : "r"(addr));
}
// fp16 mma
__device__ __forceinline__ void mma16816h(float* d, const uint32_t* a, const uint32_t* b) {
    asm volatile("mma.sync.aligned.m16n8k16.row.col.f32.f16.f16.f32 "
        "{%0,%1,%2,%3}, {%4,%5,%6,%7}, {%8,%9}, {%0,%1,%2,%3};"
        : "+f"(d[0]), "+f"(d[1]), "+f"(d[2]), "+f"(d[3])
        : "r"(a[0]), "r"(a[1]), "r"(a[2]), "r"(a[3]), "r"(b[0]), "r"(b[1]));
}
__device__ __forceinline__ uint32_t packh2(__half2 v) {
    uint32_t u; memcpy(&u, &v, 4); return u;
}

// ---------------- rope table (double-precision sincos, fp32 store) ----------
__global__ void rope_tab_kernel() {
    int idx = blockIdx.x * 256 + threadIdx.x;   // 0..131071
    int s = idx >> 5, i = idx & 31;
    double invf = pow(10000.0, -(2.0 * i) / 64.0);
    double si, co;
    sincos((double)s * invf, &si, &co);
    g_rope[s][i * 2]     = (float)co;
    g_rope[s][i * 2 + 1] = (float)si;
}

// ---------------- fused convert kernel (all 5 inputs, one launch) ----------
// b in [0,4096): x; [4096,7168): Wq/Wk/Wv (stacked); [7168,8192): Wo.
__global__ void cvt_all_kernel(const float* __restrict__ x,
                               const float* __restrict__ Wq,
                               const float* __restrict__ Wk,
                               const float* __restrict__ Wv,
                               const float* __restrict__ Wo) {
    int b = blockIdx.x;
    const float* src; __half* dst; int si, di;
    if (b < 4096) {
        si = (b * 256 + threadIdx.x) * 4;
        di = si; src = x; dst = g_x16h;
    } else if (b < 7168) {
        int bb = b - 4096;                 // 0..3071
        int mat = bb >> 10;                // 0..2
        src = (mat == 0) ? Wq : (mat == 1 ? Wk : Wv);
        si = ((bb & 1023) * 256 + threadIdx.x) * 4;
        di = (bb * 256 + threadIdx.x) * 4;
        dst = g_w16;
    } else {
        si = ((b - 7168) * 256 + threadIdx.x) * 4;
        di = si; src = Wo; dst = g_w16o;
    }
    float4 v = *(const float4*)&src[si];
    *(uint32_t*)&dst[di]     = packh2(__floats2half2_rn(v.x, v.y));
    *(uint32_t*)&dst[di + 2] = packh2(__floats2half2_rn(v.z, v.w));
}

// ------- HMMA fp16 1-pass NT GEMM (4-stage BK=32 ring, 1 sync/chunk) -------
// C[m,n] = sum_k A[m,k]*B[n,k]; BM=BN=128, BK=32, 256 threads, warps 4(M)x2(N)
// of 32x64. Stage = A+B of 128 rows x 32 cols (80 B/row stride: 16B-aligned,
// ldsm conflict-free since row addrs mod 128 are distinct). 4 stages = 81920 B
// -> 2 CTAs/SM; wait(<=2)/sync/issue c+3 gives 3 chunks of cp.async lead.
// k-slice order per accumulator identical to BK=64 version -> same numerics.
// WHICH=0: QKV; epilogue applies RoPE and stores fp16. WHICH=1: proj -> fp32.
#define SKB32 80                   // smem row stride bytes for BK=32 tiles
#define GT32  (128 * SKB32)        // 10240 B per matrix tile
#define GS32  (2 * GT32)           // A+B: 20480
#define GEMM_SMEM (4 * GS32)       // 81920
#define QSCALE 0.18033688011112042f   // 0.125 * log2(e)

__device__ __forceinline__ void gemm_issue32(int t, uint32_t st,
                                             const char* A, const char* B) {
#pragma unroll
    for (int i = 0; i < 2; i++) {
        int idx = t + i * 256;             // 0..511
        int row = idx >> 2, ch = idx & 3;  // 128 rows x 4 chunks of 16B
        cp_async16(st + row * SKB32 + ch * 16, A + (size_t)row * (DM * 2) + ch * 16);
        cp_async16(st + GT32 + row * SKB32 + ch * 16, B + (size_t)row * (DM * 2) + ch * 16);
    }
    CP_COMMIT();
}

template<int WHICH>
__global__ __launch_bounds__(256, 2)
void mma_gemm_kernel(float* __restrict__ outp) {
    constexpr int NCH = 32;        // 32 chunks of BK=32
    extern __shared__ char dsm[];
    const uint32_t sbase = smem_u32(dsm);
    const int t = threadIdx.x, lane = t & 31, wid = t >> 5;
    const int nt = blockIdx.x, mt = blockIdx.y;
    const int m0 = mt * 128, n0 = nt * 128;

    const char* pA = ((WHICH == 0) ? (const char*)g_x16h : (const char*)g_a16h)
                     + (size_t)m0 * (DM * 2);
    const char* pB = (WHICH == 0) ? (const char*)(g_w16 + (size_t)n0 * DM)
                                  : (const char*)(g_w16o + (size_t)n0 * DM);

    float acc[2][8][4];
#pragma unroll
    for (int a = 0; a < 2; a++)
#pragma unroll
        for (int b = 0; b < 8; b++)
#pragma unroll
            for (int c = 0; c < 4; c++) acc[a][b][c] = 0.f;

    // prologue: chunks 0,1,2 into stages 0,1,2  (chunk c at byte offset c*64)
#pragma unroll
    for (int c = 0; c < 3; c++)
        gemm_issue32(t, sbase + c * GS32, pA + c * 64, pB + c * 64);

    const int wm = wid & 3, wn = wid >> 2;      // 4x2 warps, 32x64 each
    const int q = lane >> 3, r = lane & 7;

    for (int c = 0; c < NCH; c++) {
        if (c <= NCH - 3)      { CP_WAIT2(); }
        else if (c == NCH - 2) { CP_WAIT1(); }
        else                   { CP_WAIT0(); }
        __syncthreads();                       // all warps done with chunk c-1
        if (c + 3 < NCH)                       // refill (c-1)'s stage with c+3
            gemm_issue32(t, sbase + ((c + 3) & 3) * GS32,
                         pA + (c + 3) * 64, pB + (c + 3) * 64);

        const uint32_t sa = sbase + (c & 3) * GS32 + (wm * 32) * SKB32;
        const uint32_t sb = sbase + (c & 3) * GS32 + GT32 + (wn * 64) * SKB32;
#pragma unroll
        for (int ks = 0; ks < 2; ks++) {
            uint32_t af[2][4], bf[4][4];
#pragma unroll
            for (int mb = 0; mb < 2; mb++)
                ldsm_x4(af[mb], sa + (mb * 16 + (q & 1) * 8 + r) * SKB32
                                   + (ks * 16 + (q >> 1) * 8) * 2);
#pragma unroll
            for (int np = 0; np < 4; np++)
                ldsm_x4(bf[np], sb + (np * 16 + (q >> 1) * 8 + r) * SKB32
                                   + (ks * 16 + (q & 1) * 8) * 2);
#pragma unroll
            for (int mb = 0; mb < 2; mb++)
#pragma unroll
                for (int np = 0; np < 4; np++) {
                    mma16816h(acc[mb][np * 2],     af[mb], &bf[np][0]);
                    mma16816h(acc[mb][np * 2 + 1], af[mb], &bf[np][2]);
                }
        }
    }

    const int rr = lane >> 2, c2 = (lane & 3) * 2;
    if (WHICH == 1) {
#pragma unroll
        for (int mb = 0; mb < 2; mb++) {
            int row0 = m0 + wm * 32 + mb * 16 + rr;
#pragma unroll
            for (int nb = 0; nb < 8; nb++) {
                int col = n0 + wn * 64 + nb * 8 + c2;
                *(float2*)&outp[(size_t)row0 * DM + col]       = make_float2(acc[mb][nb][0], acc[mb][nb][1]);
                *(float2*)&outp[(size_t)(row0 + 8) * DM + col] = make_float2(acc[mb][nb][2], acc[mb][nb][3]);
            }
        }
    } else {
        const int mat = nt >> 3;                 // 0=Q 1=K 2=V
        const int ccol = (nt & 7) * 128;
        if (mat == 2) {
            // V: plain fp16 convert
#pragma unroll
            for (int mb = 0; mb < 2; mb++) {
                int row0 = m0 + wm * 32 + mb * 16 + rr;
#pragma unroll
                for (int nb = 0; nb < 8; nb++) {
                    int col = ccol + wn * 64 + nb * 8 + c2;
                    *(uint32_t*)&g_vh[(size_t)row0 * DM + col] =
                        packh2(__floats2half2_rn(acc[mb][nb][0], acc[mb][nb][1]));
                    *(uint32_t*)&g_vh[(size_t)(row0 + 8) * DM + col] =
                        packh2(__floats2half2_rn(acc[mb][nb][2], acc[mb][nb][3]));
                }
            }
        } else {
            // Q/K: apply RoPE in fp32, store fp16 (Q pre-scaled by log2e/8).
            // Warp 64-col span = one head; pair (i, i+32) = (nb, nb+4).
            __half* dst = (mat == 0) ? g_qh : g_kh;
            const float scale = (mat == 0) ? QSCALE : 1.f;
#pragma unroll
            for (int mb = 0; mb < 2; mb++) {
                int row0 = m0 + wm * 32 + mb * 16 + rr;
#pragma unroll
                for (int nb = 0; nb < 4; nb++) {
                    int i = nb * 8 + c2;                      // head-local col (0..31)
                    float4 t0 = *(float4*)&g_rope[row0][i * 2];        // cs_i sn_i cs_i1 sn_i1
                    float4 t1 = *(float4*)&g_rope[row0 + 8][i * 2];
                    int col_lo = ccol + wn * 64 + nb * 8 + c2;
                    int col_hi = col_lo + 32;
                    {
                        float a0 = acc[mb][nb][0], b0 = acc[mb][nb + 4][0];
                        float a1 = acc[mb][nb][1], b1 = acc[mb][nb + 4][1];
                        float lo0 = (a0 * t0.x - b0 * t0.y) * scale;
                        float hi0 = (b0 * t0.x + a0 * t0.y) * scale;
                        float lo1 = (a1 * t0.z - b1 * t0.w) * scale;
                        float hi1 = (b1 * t0.z + a1 * t0.w) * scale;
                        *(uint32_t*)&dst[(size_t)row0 * DM + col_lo] = packh2(__floats2half2_rn(lo0, lo1));
                        *(uint32_t*)&dst[(size_t)row0 * DM + col_hi] = packh2(__floats2half2_rn(hi0, hi1));
                    }
                    {
                        float a0 = acc[mb][nb][2], b0 = acc[mb][nb + 4][2];
                        float a1 = acc[mb][nb][3], b1 = acc[mb][nb + 4][3];
                        float lo0 = (a0 * t1.x - b0 * t1.y) * scale;
                        float hi0 = (b0 * t1.x + a0 * t1.y) * scale;
                        float lo1 = (a1 * t1.z - b1 * t1.w) * scale;
                        float hi1 = (b1 * t1.z + a1 * t1.w) * scale;
                        *(uint32_t*)&dst[(size_t)(row0 + 8) * DM + col_lo] = packh2(__floats2half2_rn(lo0, lo1));
                        *(uint32_t*)&dst[(size_t)(row0 + 8) * DM + col_hi] = packh2(__floats2half2_rn(hi0, hi1));
                    }
                }
            }
        }
    }
}

// ---------------- Flash attention (EXACT round-10 form: 2-stage KV) ---------
// CTA = (q-tile 128 rows, head). 256 thr / 8 warps; warp = 16 q-rows x full 64 kv.
// V tile rows are 72 halves wide; cols 64..71 hold {1,0,...,0} -> row-sum via MMA.
#define SKB 144
#define F_STG 18432            // stage s at F_STG + s*F_STGSZ: Kh, Vh (9216 each)
#define F_T   9216
#define F_STGSZ 18432
#define FLASH_SMEM (18432 + 2 * F_STGSZ)   // 55296

__device__ __forceinline__ void flash_issue_kv(int t, uint32_t stg, int kbase, int h) {
    const size_t rowoff = (size_t)kbase * DM + h * 64;
    const __half* srcs[2] = {g_kh + rowoff, g_vh + rowoff};
#pragma unroll
    for (int i = 0; i < 4; i++) {
        int idx = t + i * 256;              // 0..1023
        int mat = idx >> 9;                 // 0..1
        int rem = idx & 511;
        int row = rem >> 3, ch = rem & 7;
        cp_async16(stg + mat * F_T + row * SKB + ch * 16,
                   (const char*)srcs[mat] + (size_t)row * (DM * 2) + ch * 16);
    }
    CP_COMMIT();
}

__global__ __launch_bounds__(256)
void flash_kernel() {
    extern __shared__ char dsm[];
    const uint32_t sbase = smem_u32(dsm);
    const int t = threadIdx.x, lane = t & 31, wid = t >> 5;
    const int h = blockIdx.y;
    const int qt = (int)gridDim.x - 1 - (int)blockIdx.x;   // heavy first
    const int qbase = qt * 128;
    const int ntiles = 2 * qt + 2;

    // Q load + kv tile0 (one group), then kv tile1
    {
        const size_t rowoff = (size_t)qbase * DM + h * 64;
#pragma unroll
        for (int i = 0; i < 4; i++) {
            int idx = t + i * 256;           // 0..1023
            int row = idx >> 3, ch = idx & 7;
            cp_async16(sbase + row * SKB + ch * 16,
                       (const char*)(g_qh + rowoff) + (size_t)row * (DM * 2) + ch * 16);
        }
        flash_issue_kv(t, sbase + F_STG, 0, h);            // commits Q + tile0
        flash_issue_kv(t, sbase + F_STG + F_STGSZ, 64, h); // tile 1
    }

    // Ones-column pad for both V stage buffers (bytes 128..143 of each V row;
    // cp.async only writes bytes 0..127, so this persists across stage reuse).
    if (t < 128) {
        int buf = t >> 6, row = t & 63;
        uint32_t off = F_STG + buf * F_STGSZ + F_T + row * SKB + 128;
        *(uint4*)(dsm + off) = make_uint4(0x00003C00u, 0u, 0u, 0u);  // half {1,0,...,0}
    }

    CP_WAIT1();          // Q + tile0 ready
    __syncthreads();

    // preload Q fragments (persistent)
    const int q = lane >> 3, r = lane & 7;
    const int l16 = lane & 15;
    uint32_t qf[4][4];
#pragma unroll
    for (int ks = 0; ks < 4; ks++) {
        uint32_t ro = (wid * 16 + (q & 1) * 8 + r) * SKB + (ks * 16 + (q >> 1) * 8) * 2;
        ldsm_x4(qf[ks], sbase + ro);
    }
    // hoisted ones-column B fragment (identical for all tiles / k-steps)
    uint32_t bs_ones[2];
    ldsm_x2t(bs_ones, sbase + F_STG + F_T + l16 * SKB + 128);

    float o[8][4], o_sum[4];
#pragma unroll
    for (int a = 0; a < 8; a++)
#pragma unroll
        for (int b = 0; b < 4; b++) o[a][b] = 0.f;
#pragma unroll
    for (int b = 0; b < 4; b++) o_sum[b] = 0.f;
    float m0r = -1e30f, m1r = -1e30f;

    const int rr = lane >> 2, c2 = (lane & 3) * 2;
    const int qlo = qbase + wid * 16;
    const int qr0 = qlo + rr, qr1 = qr0 + 8;

    for (int kt = 0; kt < ntiles; kt++) {
        const uint32_t stg = sbase + F_STG + (kt & 1) * F_STGSZ;

        if (kt * 64 <= qlo + 15) {     // warp tile not fully masked
            float s[8][4];
#pragma unroll
            for (int a = 0; a < 8; a++)
#pragma unroll
                for (int b = 0; b < 4; b++) s[a][b] = 0.f;

            // S = Q * K (logits in log2 domain; Q pre-scaled by log2e/8)
#pragma unroll
            for (int ks = 0; ks < 4; ks++) {
#pragma unroll
                for (int np = 0; np < 4; np++) {
                    uint32_t kf[4];
                    uint32_t ro = (np * 16 + (q >> 1) * 8 + r) * SKB + (ks * 16 + (q & 1) * 8) * 2;
                    ldsm_x4(kf, stg + 0 * F_T + ro);
                    mma16816h(s[np * 2],     qf[ks], &kf[0]);
                    mma16816h(s[np * 2 + 1], qf[ks], &kf[2]);
                }
            }

            // causal mask (diagonal-straddling tiles only)
            if (kt * 64 + 63 > qlo) {
#pragma unroll
                for (int nb = 0; nb < 8; nb++) {
                    int kc = kt * 64 + nb * 8 + c2;
                    if (kc     > qr0) s[nb][0] = -1e30f;
                    if (kc + 1 > qr0) s[nb][1] = -1e30f;
                    if (kc     > qr1) s[nb][2] = -1e30f;
                    if (kc + 1 > qr1) s[nb][3] = -1e30f;
                }
            }

            // online max (log2 domain)
            float mx0 = -1e30f, mx1 = -1e30f;
#pragma unroll
            for (int nb = 0; nb < 8; nb++) {
                mx0 = fmaxf(mx0, fmaxf(s[nb][0], s[nb][1]));
                mx1 = fmaxf(mx1, fmaxf(s[nb][2], s[nb][3]));
            }
            mx0 = fmaxf(mx0, __shfl_xor_sync(0xffffffffu, mx0, 1));
            mx0 = fmaxf(mx0, __shfl_xor_sync(0xffffffffu, mx0, 2));
            mx1 = fmaxf(mx1, __shfl_xor_sync(0xffffffffu, mx1, 1));
            mx1 = fmaxf(mx1, __shfl_xor_sync(0xffffffffu, mx1, 2));
            float mn0 = fmaxf(m0r, mx0), mn1 = fmaxf(m1r, mx1);
            float al0 = exp2f(m0r - mn0), al1 = exp2f(m1r - mn1);
            m0r = mn0;  m1r = mn1;
#pragma unroll
            for (int nb = 0; nb < 8; nb++) {
                o[nb][0] *= al0; o[nb][1] *= al0;
                o[nb][2] *= al1; o[nb][3] *= al1;
            }
            o_sum[0] *= al0; o_sum[1] *= al0;
            o_sum[2] *= al1; o_sum[3] *= al1;

            // P = exp2(s - m) computed in fp16x2; PV (+ ones-column row sum)
#pragma unroll
            for (int ks = 0; ks < 4; ks++) {
                uint32_t ph[4];
#pragma unroll
                for (int hf = 0; hf < 2; hf++) {
                    int nb = 2 * ks + hf;
                    __half2 e0 = h2exp2(__floats2half2_rn(s[nb][0] - mn0, s[nb][1] - mn0));
                    __half2 e1 = h2exp2(__floats2half2_rn(s[nb][2] - mn1, s[nb][3] - mn1));
                    ph[hf * 2]     = packh2(e0);
                    ph[hf * 2 + 1] = packh2(e1);
                }
#pragma unroll
                for (int dp = 0; dp < 4; dp++) {
                    uint32_t vf[4];
                    uint32_t ro = (ks * 16 + (q & 1) * 8 + r) * SKB + (dp * 16 + (q >> 1) * 8) * 2;
                    ldsm_x4t(vf, stg + 1 * F_T + ro);
                    mma16816h(o[dp * 2],     ph, &vf[0]);
                    mma16816h(o[dp * 2 + 1], ph, &vf[2]);
                }
                mma16816h(o_sum, ph, bs_ones);
            }
        }

        __syncthreads();          // done reading this stage
        if (kt + 2 < ntiles)
            flash_issue_kv(t, sbase + F_STG + (kt & 1) * F_STGSZ, (kt + 2) * 64, h);
        if (kt + 1 < ntiles) {
            if (kt + 2 < ntiles) { CP_WAIT1(); } else { CP_WAIT0(); }
            __syncthreads();      // tile kt+1 data visible to all
        }
    }

    // epilogue: l lives in o_sum col 0 (lanes with lane&3==0); broadcast in quad
    float l0 = __shfl_sync(0xffffffffu, o_sum[0], lane & 0x1C);
    float l1 = __shfl_sync(0xffffffffu, o_sum[2], lane & 0x1C);
    float inv0 = 1.f / l0, inv1 = 1.f / l1;
#pragma unroll
    for (int nb = 0; nb < 8; nb++) {
        int col = h * 64 + nb * 8 + c2;
        *(uint32_t*)&g_a16h[(size_t)qr0 * DM + col] =
            packh2(__floats2half2_rn(o[nb][0] * inv0, o[nb][1] * inv0));
        *(uint32_t*)&g_a16h[(size_t)qr1 * DM + col] =
            packh2(__floats2half2_rn(o[nb][2] * inv1, o[nb][3] * inv1));
    }
}

// ---------------- launch ----------------
extern "C" void kernel_launch(void* const* d_in, const int* in_sizes, int n_in,
                              void* d_out, int out_size) {
    const float* x  = (const float*)d_in[0];
    const float* Wq = (const float*)d_in[1];
    const float* Wk = (const float*)d_in[2];
    const float* Wv = (const float*)d_in[3];
    const float* Wo = (const float*)d_in[4];
    float* out = (float*)d_out;

    cudaFuncSetAttribute(mma_gemm_kernel<0>, cudaFuncAttributeMaxDynamicSharedMemorySize, GEMM_SMEM);
    cudaFuncSetAttribute(mma_gemm_kernel<1>, cudaFuncAttributeMaxDynamicSharedMemorySize, GEMM_SMEM);
    cudaFuncSetAttribute(flash_kernel,       cudaFuncAttributeMaxDynamicSharedMemorySize, FLASH_SMEM);

    rope_tab_kernel<<<512, 256>>>();
    cvt_all_kernel<<<8192, 256>>>(x, Wq, Wk, Wv, Wo);

    mma_gemm_kernel<0><<<dim3(3 * DM / 128, SEQ / 128), 256, GEMM_SMEM>>>(nullptr);

    flash_kernel<<<dim3(SEQ / 128, NH), 256, FLASH_SMEM>>>();

    mma_gemm_kernel<1><<<dim3(DM / 128, SEQ / 128), 256, GEMM_SMEM>>>(out);
}

// round 15
// speedup vs baseline: 1.0603x; 1.0603x over previous
#include <cuda_runtime.h>
#include <cuda_fp16.h>
#include <math.h>
#include <stdint.h>

// Problem constants
#define SEQ   4096
#define DM    1024
#define NH    16
#define DH    64

// ---------------- scratch (no allocations allowed) ----------------
// QKV GEMM operands (fp16, 1-pass): x, W (Wq,Wk,Wv stacked rows)
__device__ __half g_x16h[SEQ * DM];
__device__ __half g_w16[3 * DM * DM];
// proj GEMM operands (fp16, 1-pass)
__device__ __half g_w16o[DM * DM];
__device__ __half g_a16h[SEQ * DM];        // attention out (fp16)

// flash operands (fp16), written directly by the QKV epilogue
__device__ __half g_qh[SEQ * DM];   // roped Q, pre-scaled by (1/8)*log2e
__device__ __half g_kh[SEQ * DM];   // roped K
__device__ __half g_vh[SEQ * DM];   // V

// rope table: [s][i*2]=cos, [i*2+1]=sin  (i = 0..31)
__device__ float g_rope[SEQ][64];

// ---------------- low-level helpers ----------------
__device__ __forceinline__ uint32_t smem_u32(const void* p) {
    uint32_t a;
    asm("{ .reg .u64 t; cvta.to.shared.u64 t, %1; cvt.u32.u64 %0, t; }" : "=r"(a) : "l"(p));
    return a;
}
__device__ __forceinline__ void cp_async16(uint32_t sa, const void* ga) {
    asm volatile("cp.async.cg.shared.global [%0], [%1], 16;" :: "r"(sa), "l"(ga));
}
#define CP_COMMIT() asm volatile("cp.async.commit_group;" ::: "memory")
#define CP_WAIT1()  asm volatile("cp.async.wait_group 1;" ::: "memory")
#define CP_WAIT0()  asm volatile("cp.async.wait_group 0;" ::: "memory")

__device__ __forceinline__ void ldsm_x4(uint32_t* r, uint32_t addr) {
    asm volatile("ldmatrix.sync.aligned.m8n8.x4.shared.b16 {%0,%1,%2,%3}, [%4];"
        : "=r"(r[0]), "=r"(r[1]), "=r"(r[2]), "=r"(r[3]) : "r"(addr));
}
__device__ __forceinline__ void ldsm_x4t(uint32_t* r, uint32_t addr) {
    asm volatile("ldmatrix.sync.aligned.m8n8.x4.trans.shared.b16 {%0,%1,%2,%3}, [%4];"
        : "=r"(r[0]), "=r"(r[1]), "=r"(r[2]), "=r"(r[3]) : "r"(addr));
}
__device__ __forceinline__ void ldsm_x2t(uint32_t* r, uint32_t addr) {
    asm volatile("ldmatrix.sync.aligned.m8n8.x2.trans.shared.b16 {%0,%1}, [%2];"
        : "=r"(r[0]), "=r"(r[1]) : "r"(addr));
}
// fp16 mma
__device__ __forceinline__ void mma16816h(float* d, const uint32_t* a, const uint32_t* b) {
    asm volatile("mma.sync.aligned.m16n8k16.row.col.f32.f16.f16.f32 "
        "{%0,%1,%2,%3}, {%4,%5,%6,%7}, {%8,%9}, {%0,%1,%2,%3};"
        : "+f"(d[0]), "+f"(d[1]), "+f"(d[2]), "+f"(d[3])
        : "r"(a[0]), "r"(a[1]), "r"(a[2]), "r"(a[3]), "r"(b[0]), "r"(b[1]));
}
__device__ __forceinline__ uint32_t packh2(__half2 v) {
    uint32_t u; memcpy(&u, &v, 4); return u;
}

// ---------------- rope table (double-precision sincos, fp32 store) ----------
__global__ void rope_tab_kernel() {
    int idx = blockIdx.x * 256 + threadIdx.x;   // 0..131071
    int s = idx >> 5, i = idx & 31;
    double invf = pow(10000.0, -(2.0 * i) / 64.0);
    double si, co;
    sincos((double)s * invf, &si, &co);
    g_rope[s][i * 2]     = (float)co;
    g_rope[s][i * 2 + 1] = (float)si;
}

// ---------------- fused convert kernel (all 5 inputs, one launch) ----------
// b in [0,4096): x; [4096,7168): Wq/Wk/Wv (stacked); [7168,8192): Wo.
__global__ void cvt_all_kernel(const float* __restrict__ x,
                               const float* __restrict__ Wq,
                               const float* __restrict__ Wk,
                               const float* __restrict__ Wv,
                               const float* __restrict__ Wo) {
    int b = blockIdx.x;
    const float* src; __half* dst; int si, di;
    if (b < 4096) {
        si = (b * 256 + threadIdx.x) * 4;
        di = si; src = x; dst = g_x16h;
    } else if (b < 7168) {
        int bb = b - 4096;                 // 0..3071
        int mat = bb >> 10;                // 0..2
        src = (mat == 0) ? Wq : (mat == 1 ? Wk : Wv);
        si = ((bb & 1023) * 256 + threadIdx.x) * 4;
        di = (bb * 256 + threadIdx.x) * 4;
        dst = g_w16;
    } else {
        si = ((b - 7168) * 256 + threadIdx.x) * 4;
        di = si; src = Wo; dst = g_w16o;
    }
    float4 v = *(const float4*)&src[si];
    *(uint32_t*)&dst[di]     = packh2(__floats2half2_rn(v.x, v.y));
    *(uint32_t*)&dst[di + 2] = packh2(__floats2half2_rn(v.z, v.w));
}

// ---------------- QKV HMMA fp16 1-pass NT GEMM (EXACT round-10 form) -------
// C[m,n] = sum_k A[m,k]*B[n,k]; BM=BN=128, BK=64, 128 threads, 4 warps of 64x64.
// Epilogue applies RoPE and stores fp16 to g_qh/g_kh/g_vh.
#define SKB 144                    // smem row stride bytes (72 elems, conflict-free ldsm)
#define GTILE (128 * SKB)          // 18432 B per matrix tile
#define GSTAGE (2 * GTILE)         // A+B: 36864
#define GEMM_SMEM (2 * GSTAGE)     // double buffer: 73728
#define QSCALE 0.18033688011112042f   // 0.125 * log2(e)

__device__ __forceinline__ void gemm_issue(int t, uint32_t st,
                                           const char* A, const char* B) {
#pragma unroll
    for (int i = 0; i < 8; i++) {
        int idx = t + i * 128;
        int row = idx >> 3, ch = idx & 7;
        cp_async16(st + row * SKB + ch * 16, A + (size_t)row * (DM * 2) + ch * 16);
        cp_async16(st + GTILE + row * SKB + ch * 16, B + (size_t)row * (DM * 2) + ch * 16);
    }
    CP_COMMIT();
}

__global__ __launch_bounds__(128)
void qkv_gemm_kernel() {
    constexpr int NCH = 16;        // 16 chunks of BK=64
    extern __shared__ char dsm[];
    const uint32_t sbase = smem_u32(dsm);
    const int t = threadIdx.x, lane = t & 31, wid = t >> 5;
    const int nt = blockIdx.x, mt = blockIdx.y;
    const int m0 = mt * 128, n0 = nt * 128;

    const char* pA = (const char*)g_x16h;
    const char* pB = (const char*)(g_w16 + (size_t)n0 * DM);

    float acc[4][8][4];
#pragma unroll
    for (int a = 0; a < 4; a++)
#pragma unroll
        for (int b = 0; b < 8; b++)
#pragma unroll
            for (int c = 0; c < 4; c++) acc[a][b][c] = 0.f;

#pragma unroll
    for (int c = 0; c < 2; c++) {
        gemm_issue(t, sbase + (c & 1) * GSTAGE,
                   pA + (size_t)m0 * (DM * 2) + c * 128, pB + c * 128);
    }

    const int wm = wid & 1, wn = wid >> 1;      // 2x2 warps, 64x64 each
    const int q = lane >> 3, r = lane & 7;

    for (int c = 0; c < NCH; c++) {
        if (c + 1 < NCH) { CP_WAIT1(); } else { CP_WAIT0(); }
        __syncthreads();

        const uint32_t sa = sbase + (c & 1) * GSTAGE + (wm * 64) * SKB;
        const uint32_t sb = sbase + (c & 1) * GSTAGE + GTILE + (wn * 64) * SKB;
#pragma unroll
        for (int ks = 0; ks < 4; ks++) {
            uint32_t af[4][4], bf[4][4];
#pragma unroll
            for (int mb = 0; mb < 4; mb++)
                ldsm_x4(af[mb], sa + (mb * 16 + (q & 1) * 8 + r) * SKB
                                   + (ks * 16 + (q >> 1) * 8) * 2);
#pragma unroll
            for (int np = 0; np < 4; np++)
                ldsm_x4(bf[np], sb + (np * 16 + (q >> 1) * 8 + r) * SKB
                                   + (ks * 16 + (q & 1) * 8) * 2);
#pragma unroll
            for (int mb = 0; mb < 4; mb++)
#pragma unroll
                for (int np = 0; np < 4; np++) {
                    mma16816h(acc[mb][np * 2],     af[mb], &bf[np][0]);
                    mma16816h(acc[mb][np * 2 + 1], af[mb], &bf[np][2]);
                }
        }
        __syncthreads();
        if (c + 2 < NCH) {
            int cn = c + 2;
            gemm_issue(t, sbase + (cn & 1) * GSTAGE,
                       pA + (size_t)m0 * (DM * 2) + cn * 128, pB + cn * 128);
        }
    }

    const int rr = lane >> 2, c2 = (lane & 3) * 2;
    const int mat = nt >> 3;                 // 0=Q 1=K 2=V
    const int ccol = (nt & 7) * 128;
    if (mat == 2) {
        // V: plain fp16 convert
#pragma unroll
        for (int mb = 0; mb < 4; mb++) {
            int row0 = m0 + wm * 64 + mb * 16 + rr;
#pragma unroll
            for (int nb = 0; nb < 8; nb++) {
                int col = ccol + wn * 64 + nb * 8 + c2;
                *(uint32_t*)&g_vh[(size_t)row0 * DM + col] =
                    packh2(__floats2half2_rn(acc[mb][nb][0], acc[mb][nb][1]));
                *(uint32_t*)&g_vh[(size_t)(row0 + 8) * DM + col] =
                    packh2(__floats2half2_rn(acc[mb][nb][2], acc[mb][nb][3]));
            }
        }
    } else {
        // Q/K: apply RoPE in fp32, store fp16 (Q pre-scaled by log2e/8).
        // Warp 64-col span = one head; pair (i, i+32) = (nb, nb+4).
        __half* dst = (mat == 0) ? g_qh : g_kh;
        const float scale = (mat == 0) ? QSCALE : 1.f;
#pragma unroll
        for (int mb = 0; mb < 4; mb++) {
            int row0 = m0 + wm * 64 + mb * 16 + rr;
#pragma unroll
            for (int nb = 0; nb < 4; nb++) {
                int i = nb * 8 + c2;                      // head-local col (0..31)
                float4 t0 = *(float4*)&g_rope[row0][i * 2];        // cs_i sn_i cs_i1 sn_i1
                float4 t1 = *(float4*)&g_rope[row0 + 8][i * 2];
                int col_lo = ccol + wn * 64 + nb * 8 + c2;
                int col_hi = col_lo + 32;
                {
                    float a0 = acc[mb][nb][0], b0 = acc[mb][nb + 4][0];
                    float a1 = acc[mb][nb][1], b1 = acc[mb][nb + 4][1];
                    float lo0 = (a0 * t0.x - b0 * t0.y) * scale;
                    float hi0 = (b0 * t0.x + a0 * t0.y) * scale;
                    float lo1 = (a1 * t0.z - b1 * t0.w) * scale;
                    float hi1 = (b1 * t0.z + a1 * t0.w) * scale;
                    *(uint32_t*)&dst[(size_t)row0 * DM + col_lo] = packh2(__floats2half2_rn(lo0, lo1));
                    *(uint32_t*)&dst[(size_t)row0 * DM + col_hi] = packh2(__floats2half2_rn(hi0, hi1));
                }
                {
                    float a0 = acc[mb][nb][2], b0 = acc[mb][nb + 4][2];
                    float a1 = acc[mb][nb][3], b1 = acc[mb][nb + 4][3];
                    float lo0 = (a0 * t1.x - b0 * t1.y) * scale;
                    float hi0 = (b0 * t1.x + a0 * t1.y) * scale;
                    float lo1 = (a1 * t1.z - b1 * t1.w) * scale;
                    float hi1 = (b1 * t1.z + a1 * t1.w) * scale;
                    *(uint32_t*)&dst[(size_t)(row0 + 8) * DM + col_lo] = packh2(__floats2half2_rn(lo0, lo1));
                    *(uint32_t*)&dst[(size_t)(row0 + 8) * DM + col_hi] = packh2(__floats2half2_rn(hi0, hi1));
                }
            }
        }
    }
}

// ---------------- proj GEMM: BM=64, BN=128 -> 512 CTAs (occupancy fix) -----
// Same BK=64 2-stage pipeline and identical per-accumulator k-order as the
// round-10 proj (bitwise-equal numerics). Warps 2(M)x2(N) of 32x64.
#define PSTG (192 * SKB)           // A(64 rows) + B(128 rows): 27648
#define PROJ_SMEM (2 * PSTG)       // 55296 -> 4 CTAs/SM capacity

__device__ __forceinline__ void proj_issue(int t, uint32_t st,
                                           const char* A, const char* B) {
#pragma unroll
    for (int i = 0; i < 4; i++) {
        int idx = t + i * 128;             // 0..511: A, 64 rows
        int row = idx >> 3, ch = idx & 7;
        cp_async16(st + row * SKB + ch * 16, A + (size_t)row * (DM * 2) + ch * 16);
    }
#pragma unroll
    for (int i = 0; i < 8; i++) {
        int idx = t + i * 128;             // 0..1023: B, 128 rows
        int row = idx >> 3, ch = idx & 7;
        cp_async16(st + 64 * SKB + row * SKB + ch * 16,
                   B + (size_t)row * (DM * 2) + ch * 16);
    }
    CP_COMMIT();
}

__global__ __launch_bounds__(128)
void proj_kernel(float* __restrict__ outp) {
    constexpr int NCH = 16;
    extern __shared__ char dsm[];
    const uint32_t sbase = smem_u32(dsm);
    const int t = threadIdx.x, lane = t & 31, wid = t >> 5;
    const int nt = blockIdx.x, mt = blockIdx.y;
    const int m0 = mt * 64, n0 = nt * 128;

    const char* pA = (const char*)g_a16h + (size_t)m0 * (DM * 2);
    const char* pB = (const char*)(g_w16o + (size_t)n0 * DM);

    float acc[2][8][4];
#pragma unroll
    for (int a = 0; a < 2; a++)
#pragma unroll
        for (int b = 0; b < 8; b++)
#pragma unroll
            for (int c = 0; c < 4; c++) acc[a][b][c] = 0.f;

#pragma unroll
    for (int c = 0; c < 2; c++)
        proj_issue(t, sbase + c * PSTG, pA + c * 128, pB + c * 128);

    const int wm = wid & 1, wn = wid >> 1;      // 2x2 warps, 32x64 each
    const int q = lane >> 3, r = lane & 7;

    for (int c = 0; c < NCH; c++) {
        if (c + 1 < NCH) { CP_WAIT1(); } else { CP_WAIT0(); }
        __syncthreads();

        const uint32_t sa = sbase + (c & 1) * PSTG + (wm * 32) * SKB;
        const uint32_t sb = sbase + (c & 1) * PSTG + 64 * SKB + (wn * 64) * SKB;
#pragma unroll
        for (int ks = 0; ks < 4; ks++) {
            uint32_t af[2][4], bf[4][4];
#pragma unroll
            for (int mb = 0; mb < 2; mb++)
                ldsm_x4(af[mb], sa + (mb * 16 + (q & 1) * 8 + r) * SKB
                                   + (ks * 16 + (q >> 1) * 8) * 2);
#pragma unroll
            for (int np = 0; np < 4; np++)
                ldsm_x4(bf[np], sb + (np * 16 + (q >> 1) * 8 + r) * SKB
                                   + (ks * 16 + (q & 1) * 8) * 2);
#pragma unroll
            for (int mb = 0; mb < 2; mb++)
#pragma unroll
                for (int np = 0; np < 4; np++) {
                    mma16816h(acc[mb][np * 2],     af[mb], &bf[np][0]);
                    mma16816h(acc[mb][np * 2 + 1], af[mb], &bf[np][2]);
                }
        }
        __syncthreads();
        if (c + 2 < NCH) {
            int cn = c + 2;
            proj_issue(t, sbase + (cn & 1) * PSTG, pA + cn * 128, pB + cn * 128);
        }
    }

    const int rr = lane >> 2, c2 = (lane & 3) * 2;
#pragma unroll
    for (int mb = 0; mb < 2; mb++) {
        int row0 = m0 + wm * 32 + mb * 16 + rr;
#pragma unroll
        for (int nb = 0; nb < 8; nb++) {
            int col = n0 + wn * 64 + nb * 8 + c2;
            *(float2*)&outp[(size_t)row0 * DM + col]       = make_float2(acc[mb][nb][0], acc[mb][nb][1]);
            *(float2*)&outp[(size_t)(row0 + 8) * DM + col] = make_float2(acc[mb][nb][2], acc[mb][nb][3]);
        }
    }
}

// ---------------- Flash attention (EXACT round-10 form: 2-stage KV) ---------
// CTA = (q-tile 128 rows, head). 256 thr / 8 warps; warp = 16 q-rows x full 64 kv.
// V tile rows are 72 halves wide; cols 64..71 hold {1,0,...,0} -> row-sum via MMA.
#define F_STG 18432            // stage s at F_STG + s*F_STGSZ: Kh, Vh (9216 each)
#define F_T   9216
#define F_STGSZ 18432
#define FLASH_SMEM (18432 + 2 * F_STGSZ)   // 55296

__device__ __forceinline__ void flash_issue_kv(int t, uint32_t stg, int kbase, int h) {
    const size_t rowoff = (size_t)kbase * DM + h * 64;
    const __half* srcs[2] = {g_kh + rowoff, g_vh + rowoff};
#pragma unroll
    for (int i = 0; i < 4; i++) {
        int idx = t + i * 256;              // 0..1023
        int mat = idx >> 9;                 // 0..1
        int rem = idx & 511;
        int row = rem >> 3, ch = rem & 7;
        cp_async16(stg + mat * F_T + row * SKB + ch * 16,
                   (const char*)srcs[mat] + (size_t)row * (DM * 2) + ch * 16);
    }
    CP_COMMIT();
}

__global__ __launch_bounds__(256)
void flash_kernel() {
    extern __shared__ char dsm[];
    const uint32_t sbase = smem_u32(dsm);
    const int t = threadIdx.x, lane = t & 31, wid = t >> 5;
    const int h = blockIdx.y;
    const int qt = (int)gridDim.x - 1 - (int)blockIdx.x;   // heavy first
    const int qbase = qt * 128;
    const int ntiles = 2 * qt + 2;

    // Q load + kv tile0 (one group), then kv tile1
    {
        const size_t rowoff = (size_t)qbase * DM + h * 64;
#pragma unroll
        for (int i = 0; i < 4; i++) {
            int idx = t + i * 256;           // 0..1023
            int row = idx >> 3, ch = idx & 7;
            cp_async16(sbase + row * SKB + ch * 16,
                       (const char*)(g_qh + rowoff) + (size_t)row * (DM * 2) + ch * 16);
        }
        flash_issue_kv(t, sbase + F_STG, 0, h);            // commits Q + tile0
        flash_issue_kv(t, sbase + F_STG + F_STGSZ, 64, h); // tile 1
    }

    // Ones-column pad for both V stage buffers (bytes 128..143 of each V row;
    // cp.async only writes bytes 0..127, so this persists across stage reuse).
    if (t < 128) {
        int buf = t >> 6, row = t & 63;
        uint32_t off = F_STG + buf * F_STGSZ + F_T + row * SKB + 128;
        *(uint4*)(dsm + off) = make_uint4(0x00003C00u, 0u, 0u, 0u);  // half {1,0,...,0}
    }

    CP_WAIT1();          // Q + tile0 ready
    __syncthreads();

    // preload Q fragments (persistent)
    const int q = lane >> 3, r = lane & 7;
    const int l16 = lane & 15;
    uint32_t qf[4][4];
#pragma unroll
    for (int ks = 0; ks < 4; ks++) {
        uint32_t ro = (wid * 16 + (q & 1) * 8 + r) * SKB + (ks * 16 + (q >> 1) * 8) * 2;
        ldsm_x4(qf[ks], sbase + ro);
    }
    // hoisted ones-column B fragment (identical for all tiles / k-steps)
    uint32_t bs_ones[2];
    ldsm_x2t(bs_ones, sbase + F_STG + F_T + l16 * SKB + 128);

    float o[8][4], o_sum[4];
#pragma unroll
    for (int a = 0; a < 8; a++)
#pragma unroll
        for (int b = 0; b < 4; b++) o[a][b] = 0.f;
#pragma unroll
    for (int b = 0; b < 4; b++) o_sum[b] = 0.f;
    float m0r = -1e30f, m1r = -1e30f;

    const int rr = lane >> 2, c2 = (lane & 3) * 2;
    const int qlo = qbase + wid * 16;
    const int qr0 = qlo + rr, qr1 = qr0 + 8;

    for (int kt = 0; kt < ntiles; kt++) {
        const uint32_t stg = sbase + F_STG + (kt & 1) * F_STGSZ;

        if (kt * 64 <= qlo + 15) {     // warp tile not fully masked
            float s[8][4];
#pragma unroll
            for (int a = 0; a < 8; a++)
#pragma unroll
                for (int b = 0; b < 4; b++) s[a][b] = 0.f;

            // S = Q * K (logits in log2 domain; Q pre-scaled by log2e/8)
#pragma unroll
            for (int ks = 0; ks < 4; ks++) {
#pragma unroll
                for (int np = 0; np < 4; np++) {
                    uint32_t kf[4];
                    uint32_t ro = (np * 16 + (q >> 1) * 8 + r) * SKB + (ks * 16 + (q & 1) * 8) * 2;
                    ldsm_x4(kf, stg + 0 * F_T + ro);
                    mma16816h(s[np * 2],     qf[ks], &kf[0]);
                    mma16816h(s[np * 2 + 1], qf[ks], &kf[2]);
                }
            }

            // causal mask (diagonal-straddling tiles only)
            if (kt * 64 + 63 > qlo) {
#pragma unroll
                for (int nb = 0; nb < 8; nb++) {
                    int kc = kt * 64 + nb * 8 + c2;
                    if (kc     > qr0) s[nb][0] = -1e30f;
                    if (kc + 1 > qr0) s[nb][1] = -1e30f;
                    if (kc     > qr1) s[nb][2] = -1e30f;
                    if (kc + 1 > qr1) s[nb][3] = -1e30f;
                }
            }

            // online max (log2 domain)
            float mx0 = -1e30f, mx1 = -1e30f;
#pragma unroll
            for (int nb = 0; nb < 8; nb++) {
                mx0 = fmaxf(mx0, fmaxf(s[nb][0], s[nb][1]));
                mx1 = fmaxf(mx1, fmaxf(s[nb][2], s[nb][3]));
            }
            mx0 = fmaxf(mx0, __shfl_xor_sync(0xffffffffu, mx0, 1));
            mx0 = fmaxf(mx0, __shfl_xor_sync(0xffffffffu, mx0, 2));
            mx1 = fmaxf(mx1, __shfl_xor_sync(0xffffffffu, mx1, 1));
            mx1 = fmaxf(mx1, __shfl_xor_sync(0xffffffffu, mx1, 2));
            float mn0 = fmaxf(m0r, mx0), mn1 = fmaxf(m1r, mx1);
            float al0 = exp2f(m0r - mn0), al1 = exp2f(m1r - mn1);
            m0r = mn0;  m1r = mn1;
#pragma unroll
            for (int nb = 0; nb < 8; nb++) {
                o[nb][0] *= al0; o[nb][1] *= al0;
                o[nb][2] *= al1; o[nb][3] *= al1;
            }
            o_sum[0] *= al0; o_sum[1] *= al0;
            o_sum[2] *= al1; o_sum[3] *= al1;

            // P = exp2(s - m) computed in fp16x2; PV (+ ones-column row sum)
#pragma unroll
            for (int ks = 0; ks < 4; ks++) {
                uint32_t ph[4];
#pragma unroll
                for (int hf = 0; hf < 2; hf++) {
                    int nb = 2 * ks + hf;
                    __half2 e0 = h2exp2(__floats2half2_rn(s[nb][0] - mn0, s[nb][1] - mn0));
                    __half2 e1 = h2exp2(__floats2half2_rn(s[nb][2] - mn1, s[nb][3] - mn1));
                    ph[hf * 2]     = packh2(e0);
                    ph[hf * 2 + 1] = packh2(e1);
                }
#pragma unroll
                for (int dp = 0; dp < 4; dp++) {
                    uint32_t vf[4];
                    uint32_t ro = (ks * 16 + (q & 1) * 8 + r) * SKB + (dp * 16 + (q >> 1) * 8) * 2;
                    ldsm_x4t(vf, stg + 1 * F_T + ro);
                    mma16816h(o[dp * 2],     ph, &vf[0]);
                    mma16816h(o[dp * 2 + 1], ph, &vf[2]);
                }
                mma16816h(o_sum, ph, bs_ones);
            }
        }

        __syncthreads();          // done reading this stage
        if (kt + 2 < ntiles)
            flash_issue_kv(t, sbase + F_STG + (kt & 1) * F_STGSZ, (kt + 2) * 64, h);
        if (kt + 1 < ntiles) {
            if (kt + 2 < ntiles) { CP_WAIT1(); } else { CP_WAIT0(); }
            __syncthreads();      // tile kt+1 data visible to all
        }
    }

    // epilogue: l lives in o_sum col 0 (lanes with lane&3==0); broadcast in quad
    float l0 = __shfl_sync(0xffffffffu, o_sum[0], lane & 0x1C);
    float l1 = __shfl_sync(0xffffffffu, o_sum[2], lane & 0x1C);
    float inv0 = 1.f / l0, inv1 = 1.f / l1;
#pragma unroll
    for (int nb = 0; nb < 8; nb++) {
        int col = h * 64 + nb * 8 + c2;
        *(uint32_t*)&g_a16h[(size_t)qr0 * DM + col] =
            packh2(__floats2half2_rn(o[nb][0] * inv0, o[nb][1] * inv0));
        *(uint32_t*)&g_a16h[(size_t)qr1 * DM + col] =
            packh2(__floats2half2_rn(o[nb][2] * inv1, o[nb][3] * inv1));
    }
}

// ---------------- launch ----------------
extern "C" void kernel_launch(void* const* d_in, const int* in_sizes, int n_in,
                              void* d_out, int out_size) {
    const float* x  = (const float*)d_in[0];
    const float* Wq = (const float*)d_in[1];
    const float* Wk = (const float*)d_in[2];
    const float* Wv = (const float*)d_in[3];
    const float* Wo = (const float*)d_in[4];
    float* out = (float*)d_out;

    cudaFuncSetAttribute(qkv_gemm_kernel, cudaFuncAttributeMaxDynamicSharedMemorySize, GEMM_SMEM);
    cudaFuncSetAttribute(proj_kernel,     cudaFuncAttributeMaxDynamicSharedMemorySize, PROJ_SMEM);
    cudaFuncSetAttribute(flash_kernel,    cudaFuncAttributeMaxDynamicSharedMemorySize, FLASH_SMEM);

    rope_tab_kernel<<<512, 256>>>();
    cvt_all_kernel<<<8192, 256>>>(x, Wq, Wk, Wv, Wo);

    qkv_gemm_kernel<<<dim3(3 * DM / 128, SEQ / 128), 128, GEMM_SMEM>>>();

    flash_kernel<<<dim3(SEQ / 128, NH), 256, FLASH_SMEM>>>();

    proj_kernel<<<dim3(DM / 128, SEQ / 64), 128, PROJ_SMEM>>>(out);
}

// round 16
// speedup vs baseline: 1.1419x; 1.0769x over previous
#include <cuda_runtime.h>
#include <cuda_fp16.h>
#include <math.h>
#include <stdint.h>

// Problem constants
#define SEQ   4096
#define DM    1024
#define NH    16
#define DH    64

// ---------------- scratch (no allocations allowed) ----------------
// QKV GEMM operands (fp16, 1-pass): x, W (Wq,Wk,Wv stacked rows)
__device__ __half g_x16h[SEQ * DM];
__device__ __half g_w16[3 * DM * DM];
// proj GEMM operands (fp16, 1-pass)
__device__ __half g_w16o[DM * DM];
__device__ __half g_a16h[SEQ * DM];        // attention out (fp16)

// flash operands (fp16), written directly by the QKV epilogue
__device__ __half g_qh[SEQ * DM];   // roped Q, pre-scaled by (1/8)*log2e
__device__ __half g_kh[SEQ * DM];   // roped K
__device__ __half g_vh[SEQ * DM];   // V

// rope table: [s][i*2]=cos, [i*2+1]=sin  (i = 0..31)
__device__ float g_rope[SEQ][64];
// angle-decomposition part tables: s = 128a + b
__device__ float g_ropeA[32][64];   // a: cos/sin of (128a)*invf_i
__device__ float g_ropeB[128][64];  // b: cos/sin of b*invf_i

// ---------------- low-level helpers ----------------
__device__ __forceinline__ uint32_t smem_u32(const void* p) {
    uint32_t a;
    asm("{ .reg .u64 t; cvta.to.shared.u64 t, %1; cvt.u32.u64 %0, t; }" : "=r"(a) : "l"(p));
    return a;
}
__device__ __forceinline__ void cp_async16(uint32_t sa, const void* ga) {
    asm volatile("cp.async.cg.shared.global [%0], [%1], 16;" :: "r"(sa), "l"(ga));
}
#define CP_COMMIT() asm volatile("cp.async.commit_group;" ::: "memory")
#define CP_WAIT1()  asm volatile("cp.async.wait_group 1;" ::: "memory")
#define CP_WAIT0()  asm volatile("cp.async.wait_group 0;" ::: "memory")

__device__ __forceinline__ void ldsm_x4(uint32_t* r, uint32_t addr) {
    asm volatile("ldmatrix.sync.aligned.m8n8.x4.shared.b16 {%0,%1,%2,%3}, [%4];"
        : "=r"(r[0]), "=r"(r[1]), "=r"(r[2]), "=r"(r[3]) : "r"(addr));
}
__device__ __forceinline__ void ldsm_x4t(uint32_t* r, uint32_t addr) {
    asm volatile("ldmatrix.sync.aligned.m8n8.x4.trans.shared.b16 {%0,%1,%2,%3}, [%4];"
        : "=r"(r[0]), "=r"(r[1]), "=r"(r[2]), "=r"(r[3]) : "r"(addr));
}
__device__ __forceinline__ void ldsm_x2t(uint32_t* r, uint32_t addr) {
    asm volatile("ldmatrix.sync.aligned.m8n8.x2.trans.shared.b16 {%0,%1}, [%2];"
        : "=r"(r[0]), "=r"(r[1]) : "r"(addr));
}
// fp16 mma
__device__ __forceinline__ void mma16816h(float* d, const uint32_t* a, const uint32_t* b) {
    asm volatile("mma.sync.aligned.m16n8k16.row.col.f32.f16.f16.f32 "
        "{%0,%1,%2,%3}, {%4,%5,%6,%7}, {%8,%9}, {%0,%1,%2,%3};"
        : "+f"(d[0]), "+f"(d[1]), "+f"(d[2]), "+f"(d[3])
        : "r"(a[0]), "r"(a[1]), "r"(a[2]), "r"(a[3]), "r"(b[0]), "r"(b[1]));
}
__device__ __forceinline__ uint32_t packh2(__half2 v) {
    uint32_t u; memcpy(&u, &v, 4); return u;
}

// ------- rope part tables: only 5120 double sincos (32a + 128b) x 32i -------
__global__ void rope_parts_kernel() {
    int idx = blockIdx.x * 256 + threadIdx.x;   // 0..5119
    if (idx >= 5120) return;
    int i = idx & 31;
    double invf = pow(10000.0, -(2.0 * i) / 64.0);
    double si, co;
    if (idx < 1024) {                // a-table: angle = (128a) * invf
        int a = idx >> 5;
        sincos((double)(128 * a) * invf, &si, &co);
        g_ropeA[a][i * 2]     = (float)co;
        g_ropeA[a][i * 2 + 1] = (float)si;
    } else {                         // b-table: angle = b * invf
        int b = (idx - 1024) >> 5;
        sincos((double)b * invf, &si, &co);
        g_ropeB[b][i * 2]     = (float)co;
        g_ropeB[b][i * 2 + 1] = (float)si;
    }
}

// ------ fused convert + rope-combine kernel (one launch) --------------------
// b in [0,4096): x; [4096,7168): Wq/Wk/Wv (stacked); [7168,8192): Wo;
// b in [8192,8704): rope combine (angle-addition from part tables, fp32).
__global__ void cvt_all_kernel(const float* __restrict__ x,
                               const float* __restrict__ Wq,
                               const float* __restrict__ Wk,
                               const float* __restrict__ Wv,
                               const float* __restrict__ Wo) {
    int b = blockIdx.x;
    if (b >= 8192) {
        int idx = (b - 8192) * 256 + threadIdx.x;   // 0..131071
        int s = idx >> 5, i = idx & 31;
        int a = s >> 7, bb = s & 127;
        float2 A = *(float2*)&g_ropeA[a][i * 2];    // cosA, sinA
        float2 B = *(float2*)&g_ropeB[bb][i * 2];   // cosB, sinB
        g_rope[s][i * 2]     = A.x * B.x - A.y * B.y;   // cos(sum)
        g_rope[s][i * 2 + 1] = A.y * B.x + A.x * B.y;   // sin(sum)
        return;
    }
    const float* src; __half* dst; int si, di;
    if (b < 4096) {
        si = (b * 256 + threadIdx.x) * 4;
        di = si; src = x; dst = g_x16h;
    } else if (b < 7168) {
        int bb = b - 4096;                 // 0..3071
        int mat = bb >> 10;                // 0..2
        src = (mat == 0) ? Wq : (mat == 1 ? Wk : Wv);
        si = ((bb & 1023) * 256 + threadIdx.x) * 4;
        di = (bb * 256 + threadIdx.x) * 4;
        dst = g_w16;
    } else {
        si = ((b - 7168) * 256 + threadIdx.x) * 4;
        di = si; src = Wo; dst = g_w16o;
    }
    float4 v = *(const float4*)&src[si];
    *(uint32_t*)&dst[di]     = packh2(__floats2half2_rn(v.x, v.y));
    *(uint32_t*)&dst[di + 2] = packh2(__floats2half2_rn(v.z, v.w));
}

// ---------------- QKV HMMA fp16 1-pass NT GEMM (EXACT round-10 form) -------
// C[m,n] = sum_k A[m,k]*B[n,k]; BM=BN=128, BK=64, 128 threads, 4 warps of 64x64.
// Epilogue applies RoPE and stores fp16 to g_qh/g_kh/g_vh.
#define SKB 144                    // smem row stride bytes (72 elems, conflict-free ldsm)
#define GTILE (128 * SKB)          // 18432 B per matrix tile
#define GSTAGE (2 * GTILE)         // A+B: 36864
#define GEMM_SMEM (2 * GSTAGE)     // double buffer: 73728
#define QSCALE 0.18033688011112042f   // 0.125 * log2(e)

__device__ __forceinline__ void gemm_issue(int t, uint32_t st,
                                           const char* A, const char* B) {
#pragma unroll
    for (int i = 0; i < 8; i++) {
        int idx = t + i * 128;
        int row = idx >> 3, ch = idx & 7;
        cp_async16(st + row * SKB + ch * 16, A + (size_t)row * (DM * 2) + ch * 16);
        cp_async16(st + GTILE + row * SKB + ch * 16, B + (size_t)row * (DM * 2) + ch * 16);
    }
    CP_COMMIT();
}

__global__ __launch_bounds__(128)
void qkv_gemm_kernel() {
    constexpr int NCH = 16;        // 16 chunks of BK=64
    extern __shared__ char dsm[];
    const uint32_t sbase = smem_u32(dsm);
    const int t = threadIdx.x, lane = t & 31, wid = t >> 5;
    const int nt = blockIdx.x, mt = blockIdx.y;
    const int m0 = mt * 128, n0 = nt * 128;

    const char* pA = (const char*)g_x16h;
    const char* pB = (const char*)(g_w16 + (size_t)n0 * DM);

    float acc[4][8][4];
#pragma unroll
    for (int a = 0; a < 4; a++)
#pragma unroll
        for (int b = 0; b < 8; b++)
#pragma unroll
            for (int c = 0; c < 4; c++) acc[a][b][c] = 0.f;

#pragma unroll
    for (int c = 0; c < 2; c++) {
        gemm_issue(t, sbase + (c & 1) * GSTAGE,
                   pA + (size_t)m0 * (DM * 2) + c * 128, pB + c * 128);
    }

    const int wm = wid & 1, wn = wid >> 1;      // 2x2 warps, 64x64 each
    const int q = lane >> 3, r = lane & 7;

    for (int c = 0; c < NCH; c++) {
        if (c + 1 < NCH) { CP_WAIT1(); } else { CP_WAIT0(); }
        __syncthreads();

        const uint32_t sa = sbase + (c & 1) * GSTAGE + (wm * 64) * SKB;
        const uint32_t sb = sbase + (c & 1) * GSTAGE + GTILE + (wn * 64) * SKB;
#pragma unroll
        for (int ks = 0; ks < 4; ks++) {
            uint32_t af[4][4], bf[4][4];
#pragma unroll
            for (int mb = 0; mb < 4; mb++)
                ldsm_x4(af[mb], sa + (mb * 16 + (q & 1) * 8 + r) * SKB
                                   + (ks * 16 + (q >> 1) * 8) * 2);
#pragma unroll
            for (int np = 0; np < 4; np++)
                ldsm_x4(bf[np], sb + (np * 16 + (q >> 1) * 8 + r) * SKB
                                   + (ks * 16 + (q & 1) * 8) * 2);
#pragma unroll
            for (int mb = 0; mb < 4; mb++)
#pragma unroll
                for (int np = 0; np < 4; np++) {
                    mma16816h(acc[mb][np * 2],     af[mb], &bf[np][0]);
                    mma16816h(acc[mb][np * 2 + 1], af[mb], &bf[np][2]);
                }
        }
        __syncthreads();
        if (c + 2 < NCH) {
            int cn = c + 2;
            gemm_issue(t, sbase + (cn & 1) * GSTAGE,
                       pA + (size_t)m0 * (DM * 2) + cn * 128, pB + cn * 128);
        }
    }

    const int rr = lane >> 2, c2 = (lane & 3) * 2;
    const int mat = nt >> 3;                 // 0=Q 1=K 2=V
    const int ccol = (nt & 7) * 128;
    if (mat == 2) {
        // V: plain fp16 convert
#pragma unroll
        for (int mb = 0; mb < 4; mb++) {
            int row0 = m0 + wm * 64 + mb * 16 + rr;
#pragma unroll
            for (int nb = 0; nb < 8; nb++) {
                int col = ccol + wn * 64 + nb * 8 + c2;
                *(uint32_t*)&g_vh[(size_t)row0 * DM + col] =
                    packh2(__floats2half2_rn(acc[mb][nb][0], acc[mb][nb][1]));
                *(uint32_t*)&g_vh[(size_t)(row0 + 8) * DM + col] =
                    packh2(__floats2half2_rn(acc[mb][nb][2], acc[mb][nb][3]));
            }
        }
    } else {
        // Q/K: apply RoPE in fp32, store fp16 (Q pre-scaled by log2e/8).
        // Warp 64-col span = one head; pair (i, i+32) = (nb, nb+4).
        __half* dst = (mat == 0) ? g_qh : g_kh;
        const float scale = (mat == 0) ? QSCALE : 1.f;
#pragma unroll
        for (int mb = 0; mb < 4; mb++) {
            int row0 = m0 + wm * 64 + mb * 16 + rr;
#pragma unroll
            for (int nb = 0; nb < 4; nb++) {
                int i = nb * 8 + c2;                      // head-local col (0..31)
                float4 t0 = *(float4*)&g_rope[row0][i * 2];        // cs_i sn_i cs_i1 sn_i1
                float4 t1 = *(float4*)&g_rope[row0 + 8][i * 2];
                int col_lo = ccol + wn * 64 + nb * 8 + c2;
                int col_hi = col_lo + 32;
                {
                    float a0 = acc[mb][nb][0], b0 = acc[mb][nb + 4][0];
                    float a1 = acc[mb][nb][1], b1 = acc[mb][nb + 4][1];
                    float lo0 = (a0 * t0.x - b0 * t0.y) * scale;
                    float hi0 = (b0 * t0.x + a0 * t0.y) * scale;
                    float lo1 = (a1 * t0.z - b1 * t0.w) * scale;
                    float hi1 = (b1 * t0.z + a1 * t0.w) * scale;
                    *(uint32_t*)&dst[(size_t)row0 * DM + col_lo] = packh2(__floats2half2_rn(lo0, lo1));
                    *(uint32_t*)&dst[(size_t)row0 * DM + col_hi] = packh2(__floats2half2_rn(hi0, hi1));
                }
                {
                    float a0 = acc[mb][nb][2], b0 = acc[mb][nb + 4][2];
                    float a1 = acc[mb][nb][3], b1 = acc[mb][nb + 4][3];
                    float lo0 = (a0 * t1.x - b0 * t1.y) * scale;
                    float hi0 = (b0 * t1.x + a0 * t1.y) * scale;
                    float lo1 = (a1 * t1.z - b1 * t1.w) * scale;
                    float hi1 = (b1 * t1.z + a1 * t1.w) * scale;
                    *(uint32_t*)&dst[(size_t)(row0 + 8) * DM + col_lo] = packh2(__floats2half2_rn(lo0, lo1));
                    *(uint32_t*)&dst[(size_t)(row0 + 8) * DM + col_hi] = packh2(__floats2half2_rn(hi0, hi1));
                }
            }
        }
    }
}

// ---------------- proj GEMM: BM=64, BN=128 -> 512 CTAs (R15 form) ----------
#define PSTG (192 * SKB)           // A(64 rows) + B(128 rows): 27648
#define PROJ_SMEM (2 * PSTG)       // 55296 -> 4 CTAs/SM capacity

__device__ __forceinline__ void proj_issue(int t, uint32_t st,
                                           const char* A, const char* B) {
#pragma unroll
    for (int i = 0; i < 4; i++) {
        int idx = t + i * 128;             // 0..511: A, 64 rows
        int row = idx >> 3, ch = idx & 7;
        cp_async16(st + row * SKB + ch * 16, A + (size_t)row * (DM * 2) + ch * 16);
    }
#pragma unroll
    for (int i = 0; i < 8; i++) {
        int idx = t + i * 128;             // 0..1023: B, 128 rows
        int row = idx >> 3, ch = idx & 7;
        cp_async16(st + 64 * SKB + row * SKB + ch * 16,
                   B + (size_t)row * (DM * 2) + ch * 16);
    }
    CP_COMMIT();
}

__global__ __launch_bounds__(128)
void proj_kernel(float* __restrict__ outp) {
    constexpr int NCH = 16;
    extern __shared__ char dsm[];
    const uint32_t sbase = smem_u32(dsm);
    const int t = threadIdx.x, lane = t & 31, wid = t >> 5;
    const int nt = blockIdx.x, mt = blockIdx.y;
    const int m0 = mt * 64, n0 = nt * 128;

    const char* pA = (const char*)g_a16h + (size_t)m0 * (DM * 2);
    const char* pB = (const char*)(g_w16o + (size_t)n0 * DM);

    float acc[2][8][4];
#pragma unroll
    for (int a = 0; a < 2; a++)
#pragma unroll
        for (int b = 0; b < 8; b++)
#pragma unroll
            for (int c = 0; c < 4; c++) acc[a][b][c] = 0.f;

#pragma unroll
    for (int c = 0; c < 2; c++)
        proj_issue(t, sbase + c * PSTG, pA + c * 128, pB + c * 128);

    const int wm = wid & 1, wn = wid >> 1;      // 2x2 warps, 32x64 each
    const int q = lane >> 3, r = lane & 7;

    for (int c = 0; c < NCH; c++) {
        if (c + 1 < NCH) { CP_WAIT1(); } else { CP_WAIT0(); }
        __syncthreads();

        const uint32_t sa = sbase + (c & 1) * PSTG + (wm * 32) * SKB;
        const uint32_t sb = sbase + (c & 1) * PSTG + 64 * SKB + (wn * 64) * SKB;
#pragma unroll
        for (int ks = 0; ks < 4; ks++) {
            uint32_t af[2][4], bf[4][4];
#pragma unroll
            for (int mb = 0; mb < 2; mb++)
                ldsm_x4(af[mb], sa + (mb * 16 + (q & 1) * 8 + r) * SKB
                                   + (ks * 16 + (q >> 1) * 8) * 2);
#pragma unroll
            for (int np = 0; np < 4; np++)
                ldsm_x4(bf[np], sb + (np * 16 + (q >> 1) * 8 + r) * SKB
                                   + (ks * 16 + (q & 1) * 8) * 2);
#pragma unroll
            for (int mb = 0; mb < 2; mb++)
#pragma unroll
                for (int np = 0; np < 4; np++) {
                    mma16816h(acc[mb][np * 2],     af[mb], &bf[np][0]);
                    mma16816h(acc[mb][np * 2 + 1], af[mb], &bf[np][2]);
                }
        }
        __syncthreads();
        if (c + 2 < NCH) {
            int cn = c + 2;
            proj_issue(t, sbase + (cn & 1) * PSTG, pA + cn * 128, pB + cn * 128);
        }
    }

    const int rr = lane >> 2, c2 = (lane & 3) * 2;
#pragma unroll
    for (int mb = 0; mb < 2; mb++) {
        int row0 = m0 + wm * 32 + mb * 16 + rr;
#pragma unroll
        for (int nb = 0; nb < 8; nb++) {
            int col = n0 + wn * 64 + nb * 8 + c2;
            *(float2*)&outp[(size_t)row0 * DM + col]       = make_float2(acc[mb][nb][0], acc[mb][nb][1]);
            *(float2*)&outp[(size_t)(row0 + 8) * DM + col] = make_float2(acc[mb][nb][2], acc[mb][nb][3]);
        }
    }
}

// ---------------- Flash attention (EXACT round-10 form: 2-stage KV) ---------
// CTA = (q-tile 128 rows, head). 256 thr / 8 warps; warp = 16 q-rows x full 64 kv.
// V tile rows are 72 halves wide; cols 64..71 hold {1,0,...,0} -> row-sum via MMA.
#define F_STG 18432            // stage s at F_STG + s*F_STGSZ: Kh, Vh (9216 each)
#define F_T   9216
#define F_STGSZ 18432
#define FLASH_SMEM (18432 + 2 * F_STGSZ)   // 55296

__device__ __forceinline__ void flash_issue_kv(int t, uint32_t stg, int kbase, int h) {
    const size_t rowoff = (size_t)kbase * DM + h * 64;
    const __half* srcs[2] = {g_kh + rowoff, g_vh + rowoff};
#pragma unroll
    for (int i = 0; i < 4; i++) {
        int idx = t + i * 256;              // 0..1023
        int mat = idx >> 9;                 // 0..1
        int rem = idx & 511;
        int row = rem >> 3, ch = rem & 7;
        cp_async16(stg + mat * F_T + row * SKB + ch * 16,
                   (const char*)srcs[mat] + (size_t)row * (DM * 2) + ch * 16);
    }
    CP_COMMIT();
}

__global__ __launch_bounds__(256)
void flash_kernel() {
    extern __shared__ char dsm[];
    const uint32_t sbase = smem_u32(dsm);
    const int t = threadIdx.x, lane = t & 31, wid = t >> 5;
    const int h = blockIdx.y;
    const int qt = (int)gridDim.x - 1 - (int)blockIdx.x;   // heavy first
    const int qbase = qt * 128;
    const int ntiles = 2 * qt + 2;

    // Q load + kv tile0 (one group), then kv tile1
    {
        const size_t rowoff = (size_t)qbase * DM + h * 64;
#pragma unroll
        for (int i = 0; i < 4; i++) {
            int idx = t + i * 256;           // 0..1023
            int row = idx >> 3, ch = idx & 7;
            cp_async16(sbase + row * SKB + ch * 16,
                       (const char*)(g_qh + rowoff) + (size_t)row * (DM * 2) + ch * 16);
        }
        flash_issue_kv(t, sbase + F_STG, 0, h);            // commits Q + tile0
        flash_issue_kv(t, sbase + F_STG + F_STGSZ, 64, h); // tile 1
    }

    // Ones-column pad for both V stage buffers (bytes 128..143 of each V row;
    // cp.async only writes bytes 0..127, so this persists across stage reuse).
    if (t < 128) {
        int buf = t >> 6, row = t & 63;
        uint32_t off = F_STG + buf * F_STGSZ + F_T + row * SKB + 128;
        *(uint4*)(dsm + off) = make_uint4(0x00003C00u, 0u, 0u, 0u);  // half {1,0,...,0}
    }

    CP_WAIT1();          // Q + tile0 ready
    __syncthreads();

    // preload Q fragments (persistent)
    const int q = lane >> 3, r = lane & 7;
    const int l16 = lane & 15;
    uint32_t qf[4][4];
#pragma unroll
    for (int ks = 0; ks < 4; ks++) {
        uint32_t ro = (wid * 16 + (q & 1) * 8 + r) * SKB + (ks * 16 + (q >> 1) * 8) * 2;
        ldsm_x4(qf[ks], sbase + ro);
    }
    // hoisted ones-column B fragment (identical for all tiles / k-steps)
    uint32_t bs_ones[2];
    ldsm_x2t(bs_ones, sbase + F_STG + F_T + l16 * SKB + 128);

    float o[8][4], o_sum[4];
#pragma unroll
    for (int a = 0; a < 8; a++)
#pragma unroll
        for (int b = 0; b < 4; b++) o[a][b] = 0.f;
#pragma unroll
    for (int b = 0; b < 4; b++) o_sum[b] = 0.f;
    float m0r = -1e30f, m1r = -1e30f;

    const int rr = lane >> 2, c2 = (lane & 3) * 2;
    const int qlo = qbase + wid * 16;
    const int qr0 = qlo + rr, qr1 = qr0 + 8;

    for (int kt = 0; kt < ntiles; kt++) {
        const uint32_t stg = sbase + F_STG + (kt & 1) * F_STGSZ;

        if (kt * 64 <= qlo + 15) {     // warp tile not fully masked
            float s[8][4];
#pragma unroll
            for (int a = 0; a < 8; a++)
#pragma unroll
                for (int b = 0; b < 4; b++) s[a][b] = 0.f;

            // S = Q * K (logits in log2 domain; Q pre-scaled by log2e/8)
#pragma unroll
            for (int ks = 0; ks < 4; ks++) {
#pragma unroll
                for (int np = 0; np < 4; np++) {
                    uint32_t kf[4];
                    uint32_t ro = (np * 16 + (q >> 1) * 8 + r) * SKB + (ks * 16 + (q & 1) * 8) * 2;
                    ldsm_x4(kf, stg + 0 * F_T + ro);
                    mma16816h(s[np * 2],     qf[ks], &kf[0]);
                    mma16816h(s[np * 2 + 1], qf[ks], &kf[2]);
                }
            }

            // causal mask (diagonal-straddling tiles only)
            if (kt * 64 + 63 > qlo) {
#pragma unroll
                for (int nb = 0; nb < 8; nb++) {
                    int kc = kt * 64 + nb * 8 + c2;
                    if (kc     > qr0) s[nb][0] = -1e30f;
                    if (kc + 1 > qr0) s[nb][1] = -1e30f;
                    if (kc     > qr1) s[nb][2] = -1e30f;
                    if (kc + 1 > qr1) s[nb][3] = -1e30f;
                }
            }

            // online max (log2 domain)
            float mx0 = -1e30f, mx1 = -1e30f;
#pragma unroll
            for (int nb = 0; nb < 8; nb++) {
                mx0 = fmaxf(mx0, fmaxf(s[nb][0], s[nb][1]));
                mx1 = fmaxf(mx1, fmaxf(s[nb][2], s[nb][3]));
            }
            mx0 = fmaxf(mx0, __shfl_xor_sync(0xffffffffu, mx0, 1));
            mx0 = fmaxf(mx0, __shfl_xor_sync(0xffffffffu, mx0, 2));
            mx1 = fmaxf(mx1, __shfl_xor_sync(0xffffffffu, mx1, 1));
            mx1 = fmaxf(mx1, __shfl_xor_sync(0xffffffffu, mx1, 2));
            float mn0 = fmaxf(m0r, mx0), mn1 = fmaxf(m1r, mx1);
            float al0 = exp2f(m0r - mn0), al1 = exp2f(m1r - mn1);
            m0r = mn0;  m1r = mn1;
#pragma unroll
            for (int nb = 0; nb < 8; nb++) {
                o[nb][0] *= al0; o[nb][1] *= al0;
                o[nb][2] *= al1; o[nb][3] *= al1;
            }
            o_sum[0] *= al0; o_sum[1] *= al0;
            o_sum[2] *= al1; o_sum[3] *= al1;

            // P = exp2(s - m) computed in fp16x2; PV (+ ones-column row sum)
#pragma unroll
            for (int ks = 0; ks < 4; ks++) {
                uint32_t ph[4];
#pragma unroll
                for (int hf = 0; hf < 2; hf++) {
                    int nb = 2 * ks + hf;
                    __half2 e0 = h2exp2(__floats2half2_rn(s[nb][0] - mn0, s[nb][1] - mn0));
                    __half2 e1 = h2exp2(__floats2half2_rn(s[nb][2] - mn1, s[nb][3] - mn1));
                    ph[hf * 2]     = packh2(e0);
                    ph[hf * 2 + 1] = packh2(e1);
                }
#pragma unroll
                for (int dp = 0; dp < 4; dp++) {
                    uint32_t vf[4];
                    uint32_t ro = (ks * 16 + (q & 1) * 8 + r) * SKB + (dp * 16 + (q >> 1) * 8) * 2;
                    ldsm_x4t(vf, stg + 1 * F_T + ro);
                    mma16816h(o[dp * 2],     ph, &vf[0]);
                    mma16816h(o[dp * 2 + 1], ph, &vf[2]);
                }
                mma16816h(o_sum, ph, bs_ones);
            }
        }

        __syncthreads();          // done reading this stage
        if (kt + 2 < ntiles)
            flash_issue_kv(t, sbase + F_STG + (kt & 1) * F_STGSZ, (kt + 2) * 64, h);
        if (kt + 1 < ntiles) {
            if (kt + 2 < ntiles) { CP_WAIT1(); } else { CP_WAIT0(); }
            __syncthreads();      // tile kt+1 data visible to all
        }
    }

    // epilogue: l lives in o_sum col 0 (lanes with lane&3==0); broadcast in quad
    float l0 = __shfl_sync(0xffffffffu, o_sum[0], lane & 0x1C);
    float l1 = __shfl_sync(0xffffffffu, o_sum[2], lane & 0x1C);
    float inv0 = 1.f / l0, inv1 = 1.f / l1;
#pragma unroll
    for (int nb = 0; nb < 8; nb++) {
        int col = h * 64 + nb * 8 + c2;
        *(uint32_t*)&g_a16h[(size_t)qr0 * DM + col] =
            packh2(__floats2half2_rn(o[nb][0] * inv0, o[nb][1] * inv0));
        *(uint32_t*)&g_a16h[(size_t)qr1 * DM + col] =
            packh2(__floats2half2_rn(o[nb][2] * inv1, o[nb][3] * inv1));
    }
}

// ---------------- launch ----------------
extern "C" void kernel_launch(void* const* d_in, const int* in_sizes, int n_in,
                              void* d_out, int out_size) {
    const float* x  = (const float*)d_in[0];
    const float* Wq = (const float*)d_in[1];
    const float* Wk = (const float*)d_in[2];
    const float* Wv = (const float*)d_in[3];
    const float* Wo = (const float*)d_in[4];
    float* out = (float*)d_out;

    cudaFuncSetAttribute(qkv_gemm_kernel, cudaFuncAttributeMaxDynamicSharedMemorySize, GEMM_SMEM);
    cudaFuncSetAttribute(proj_kernel,     cudaFuncAttributeMaxDynamicSharedMemorySize, PROJ_SMEM);
    cudaFuncSetAttribute(flash_kernel,    cudaFuncAttributeMaxDynamicSharedMemorySize, FLASH_SMEM);

    rope_parts_kernel<<<20, 256>>>();
    cvt_all_kernel<<<8704, 256>>>(x, Wq, Wk, Wv, Wo);

    qkv_gemm_kernel<<<dim3(3 * DM / 128, SEQ / 128), 128, GEMM_SMEM>>>();

    flash_kernel<<<dim3(SEQ / 128, NH), 256, FLASH_SMEM>>>();

    proj_kernel<<<dim3(DM / 128, SEQ / 64), 128, PROJ_SMEM>>>(out);
}

// round 17
// speedup vs baseline: 1.2104x; 1.0600x over previous
#include <cuda_runtime.h>
#include <cuda_fp16.h>
#include <math.h>
#include <stdint.h>

// Problem constants
#define SEQ   4096
#define DM    1024
#define NH    16
#define DH    64

// ---------------- scratch (no allocations allowed) ----------------
// QKV GEMM operands (fp16, 1-pass): x, W (Wq,Wk,Wv stacked rows)
__device__ __half g_x16h[SEQ * DM];
__device__ __half g_w16[3 * DM * DM];
// proj GEMM operands (fp16, 1-pass)
__device__ __half g_w16o[DM * DM];
__device__ __half g_a16h[SEQ * DM];        // attention out (fp16)

// flash operands (fp16), written directly by the QKV epilogue
__device__ __half g_qh[SEQ * DM];   // roped Q, pre-scaled by (1/8)*log2e
__device__ __half g_kh[SEQ * DM];   // roped K
__device__ __half g_vh[SEQ * DM];   // V

// rope table: [s][i*2]=cos, [i*2+1]=sin  (i = 0..31)
__device__ float g_rope[SEQ][64];
// angle-decomposition part tables: s = 128a + b
__device__ float g_ropeA[32][64];   // a: cos/sin of (128a)*invf_i
__device__ float g_ropeB[128][64];  // b: cos/sin of b*invf_i

// ---------------- low-level helpers ----------------
__device__ __forceinline__ uint32_t smem_u32(const void* p) {
    uint32_t a;
    asm("{ .reg .u64 t; cvta.to.shared.u64 t, %1; cvt.u32.u64 %0, t; }" : "=r"(a) : "l"(p));
    return a;
}
__device__ __forceinline__ void cp_async16(uint32_t sa, const void* ga) {
    asm volatile("cp.async.cg.shared.global [%0], [%1], 16;" :: "r"(sa), "l"(ga));
}
#define CP_COMMIT() asm volatile("cp.async.commit_group;" ::: "memory")
#define CP_WAIT1()  asm volatile("cp.async.wait_group 1;" ::: "memory")
#define CP_WAIT0()  asm volatile("cp.async.wait_group 0;" ::: "memory")

__device__ __forceinline__ void ldsm_x4(uint32_t* r, uint32_t addr) {
    asm volatile("ldmatrix.sync.aligned.m8n8.x4.shared.b16 {%0,%1,%2,%3}, [%4];"
        : "=r"(r[0]), "=r"(r[1]), "=r"(r[2]), "=r"(r[3]) : "r"(addr));
}
__device__ __forceinline__ void ldsm_x4t(uint32_t* r, uint32_t addr) {
    asm volatile("ldmatrix.sync.aligned.m8n8.x4.trans.shared.b16 {%0,%1,%2,%3}, [%4];"
        : "=r"(r[0]), "=r"(r[1]), "=r"(r[2]), "=r"(r[3]) : "r"(addr));
}
__device__ __forceinline__ void ldsm_x2t(uint32_t* r, uint32_t addr) {
    asm volatile("ldmatrix.sync.aligned.m8n8.x2.trans.shared.b16 {%0,%1}, [%2];"
        : "=r"(r[0]), "=r"(r[1]) : "r"(addr));
}
// fp16 mma
__device__ __forceinline__ void mma16816h(float* d, const uint32_t* a, const uint32_t* b) {
    asm volatile("mma.sync.aligned.m16n8k16.row.col.f32.f16.f16.f32 "
        "{%0,%1,%2,%3}, {%4,%5,%6,%7}, {%8,%9}, {%0,%1,%2,%3};"
        : "+f"(d[0]), "+f"(d[1]), "+f"(d[2]), "+f"(d[3])
        : "r"(a[0]), "r"(a[1]), "r"(a[2]), "r"(a[3]), "r"(b[0]), "r"(b[1]));
}
__device__ __forceinline__ uint32_t packh2(__half2 v) {
    uint32_t u; memcpy(&u, &v, 4); return u;
}

// ------- rope part tables: only 5120 double sincos (32a + 128b) x 32i -------
__global__ void rope_parts_kernel() {
    int idx = blockIdx.x * 256 + threadIdx.x;   // 0..5119
    if (idx >= 5120) return;
    int i = idx & 31;
    double invf = pow(10000.0, -(2.0 * i) / 64.0);
    double si, co;
    if (idx < 1024) {                // a-table: angle = (128a) * invf
        int a = idx >> 5;
        sincos((double)(128 * a) * invf, &si, &co);
        g_ropeA[a][i * 2]     = (float)co;
        g_ropeA[a][i * 2 + 1] = (float)si;
    } else {                         // b-table: angle = b * invf
        int b = (idx - 1024) >> 5;
        sincos((double)b * invf, &si, &co);
        g_ropeB[b][i * 2]     = (float)co;
        g_ropeB[b][i * 2 + 1] = (float)si;
    }
}

// ------ fused convert + rope-combine kernel (one launch) --------------------
// b in [0,4096): x; [4096,7168): Wq/Wk/Wv (stacked); [7168,8192): Wo;
// b in [8192,8704): rope combine (angle-addition from part tables, fp32).
__global__ void cvt_all_kernel(const float* __restrict__ x,
                               const float* __restrict__ Wq,
                               const float* __restrict__ Wk,
                               const float* __restrict__ Wv,
                               const float* __restrict__ Wo) {
    int b = blockIdx.x;
    if (b >= 8192) {
        int idx = (b - 8192) * 256 + threadIdx.x;   // 0..131071
        int s = idx >> 5, i = idx & 31;
        int a = s >> 7, bb = s & 127;
        float2 A = *(float2*)&g_ropeA[a][i * 2];    // cosA, sinA
        float2 B = *(float2*)&g_ropeB[bb][i * 2];   // cosB, sinB
        g_rope[s][i * 2]     = A.x * B.x - A.y * B.y;   // cos(sum)
        g_rope[s][i * 2 + 1] = A.y * B.x + A.x * B.y;   // sin(sum)
        return;
    }
    const float* src; __half* dst; int si, di;
    if (b < 4096) {
        si = (b * 256 + threadIdx.x) * 4;
        di = si; src = x; dst = g_x16h;
    } else if (b < 7168) {
        int bb = b - 4096;                 // 0..3071
        int mat = bb >> 10;                // 0..2
        src = (mat == 0) ? Wq : (mat == 1 ? Wk : Wv);
        si = ((bb & 1023) * 256 + threadIdx.x) * 4;
        di = (bb * 256 + threadIdx.x) * 4;
        dst = g_w16;
    } else {
        si = ((b - 7168) * 256 + threadIdx.x) * 4;
        di = si; src = Wo; dst = g_w16o;
    }
    float4 v = *(const float4*)&src[si];
    *(uint32_t*)&dst[di]     = packh2(__floats2half2_rn(v.x, v.y));
    *(uint32_t*)&dst[di + 2] = packh2(__floats2half2_rn(v.z, v.w));
}

// ---------------- QKV HMMA fp16 1-pass NT GEMM (EXACT round-10 form) -------
// C[m,n] = sum_k A[m,k]*B[n,k]; BM=BN=128, BK=64, 128 threads, 4 warps of 64x64.
// Epilogue applies RoPE and stores fp16 to g_qh/g_kh/g_vh.
#define SKB 144                    // smem row stride bytes (72 elems, conflict-free ldsm)
#define GTILE (128 * SKB)          // 18432 B per matrix tile
#define GSTAGE (2 * GTILE)         // A+B: 36864
#define GEMM_SMEM (2 * GSTAGE)     // double buffer: 73728
#define QSCALE 0.18033688011112042f   // 0.125 * log2(e)

__device__ __forceinline__ void gemm_issue(int t, uint32_t st,
                                           const char* A, const char* B) {
#pragma unroll
    for (int i = 0; i < 8; i++) {
        int idx = t + i * 128;
        int row = idx >> 3, ch = idx & 7;
        cp_async16(st + row * SKB + ch * 16, A + (size_t)row * (DM * 2) + ch * 16);
        cp_async16(st + GTILE + row * SKB + ch * 16, B + (size_t)row * (DM * 2) + ch * 16);
    }
    CP_COMMIT();
}

__global__ __launch_bounds__(128)
void qkv_gemm_kernel() {
    constexpr int NCH = 16;        // 16 chunks of BK=64
    extern __shared__ char dsm[];
    const uint32_t sbase = smem_u32(dsm);
    const int t = threadIdx.x, lane = t & 31, wid = t >> 5;
    const int nt = blockIdx.x, mt = blockIdx.y;
    const int m0 = mt * 128, n0 = nt * 128;

    const char* pA = (const char*)g_x16h;
    const char* pB = (const char*)(g_w16 + (size_t)n0 * DM);

    float acc[4][8][4];
#pragma unroll
    for (int a = 0; a < 4; a++)
#pragma unroll
        for (int b = 0; b < 8; b++)
#pragma unroll
            for (int c = 0; c < 4; c++) acc[a][b][c] = 0.f;

#pragma unroll
    for (int c = 0; c < 2; c++) {
        gemm_issue(t, sbase + (c & 1) * GSTAGE,
                   pA + (size_t)m0 * (DM * 2) + c * 128, pB + c * 128);
    }

    const int wm = wid & 1, wn = wid >> 1;      // 2x2 warps, 64x64 each
    const int q = lane >> 3, r = lane & 7;

    for (int c = 0; c < NCH; c++) {
        if (c + 1 < NCH) { CP_WAIT1(); } else { CP_WAIT0(); }
        __syncthreads();

        const uint32_t sa = sbase + (c & 1) * GSTAGE + (wm * 64) * SKB;
        const uint32_t sb = sbase + (c & 1) * GSTAGE + GTILE + (wn * 64) * SKB;
#pragma unroll
        for (int ks = 0; ks < 4; ks++) {
            uint32_t af[4][4], bf[4][4];
#pragma unroll
            for (int mb = 0; mb < 4; mb++)
                ldsm_x4(af[mb], sa + (mb * 16 + (q & 1) * 8 + r) * SKB
                                   + (ks * 16 + (q >> 1) * 8) * 2);
#pragma unroll
            for (int np = 0; np < 4; np++)
                ldsm_x4(bf[np], sb + (np * 16 + (q >> 1) * 8 + r) * SKB
                                   + (ks * 16 + (q & 1) * 8) * 2);
#pragma unroll
            for (int mb = 0; mb < 4; mb++)
#pragma unroll
                for (int np = 0; np < 4; np++) {
                    mma16816h(acc[mb][np * 2],     af[mb], &bf[np][0]);
                    mma16816h(acc[mb][np * 2 + 1], af[mb], &bf[np][2]);
                }
        }
        __syncthreads();
        if (c + 2 < NCH) {
            int cn = c + 2;
            gemm_issue(t, sbase + (cn & 1) * GSTAGE,
                       pA + (size_t)m0 * (DM * 2) + cn * 128, pB + cn * 128);
        }
    }

    const int rr = lane >> 2, c2 = (lane & 3) * 2;
    const int mat = nt >> 3;                 // 0=Q 1=K 2=V
    const int ccol = (nt & 7) * 128;
    if (mat == 2) {
        // V: plain fp16 convert
#pragma unroll
        for (int mb = 0; mb < 4; mb++) {
            int row0 = m0 + wm * 64 + mb * 16 + rr;
#pragma unroll
            for (int nb = 0; nb < 8; nb++) {
                int col = ccol + wn * 64 + nb * 8 + c2;
                *(uint32_t*)&g_vh[(size_t)row0 * DM + col] =
                    packh2(__floats2half2_rn(acc[mb][nb][0], acc[mb][nb][1]));
                *(uint32_t*)&g_vh[(size_t)(row0 + 8) * DM + col] =
                    packh2(__floats2half2_rn(acc[mb][nb][2], acc[mb][nb][3]));
            }
        }
    } else {
        // Q/K: apply RoPE in fp32, store fp16 (Q pre-scaled by log2e/8).
        // Warp 64-col span = one head; pair (i, i+32) = (nb, nb+4).
        __half* dst = (mat == 0) ? g_qh : g_kh;
        const float scale = (mat == 0) ? QSCALE : 1.f;
#pragma unroll
        for (int mb = 0; mb < 4; mb++) {
            int row0 = m0 + wm * 64 + mb * 16 + rr;
#pragma unroll
            for (int nb = 0; nb < 4; nb++) {
                int i = nb * 8 + c2;                      // head-local col (0..31)
                float4 t0 = *(float4*)&g_rope[row0][i * 2];        // cs_i sn_i cs_i1 sn_i1
                float4 t1 = *(float4*)&g_rope[row0 + 8][i * 2];
                int col_lo = ccol + wn * 64 + nb * 8 + c2;
                int col_hi = col_lo + 32;
                {
                    float a0 = acc[mb][nb][0], b0 = acc[mb][nb + 4][0];
                    float a1 = acc[mb][nb][1], b1 = acc[mb][nb + 4][1];
                    float lo0 = (a0 * t0.x - b0 * t0.y) * scale;
                    float hi0 = (b0 * t0.x + a0 * t0.y) * scale;
                    float lo1 = (a1 * t0.z - b1 * t0.w) * scale;
                    float hi1 = (b1 * t0.z + a1 * t0.w) * scale;
                    *(uint32_t*)&dst[(size_t)row0 * DM + col_lo] = packh2(__floats2half2_rn(lo0, lo1));
                    *(uint32_t*)&dst[(size_t)row0 * DM + col_hi] = packh2(__floats2half2_rn(hi0, hi1));
                }
                {
                    float a0 = acc[mb][nb][2], b0 = acc[mb][nb + 4][2];
                    float a1 = acc[mb][nb][3], b1 = acc[mb][nb + 4][3];
                    float lo0 = (a0 * t1.x - b0 * t1.y) * scale;
                    float hi0 = (b0 * t1.x + a0 * t1.y) * scale;
                    float lo1 = (a1 * t1.z - b1 * t1.w) * scale;
                    float hi1 = (b1 * t1.z + a1 * t1.w) * scale;
                    *(uint32_t*)&dst[(size_t)(row0 + 8) * DM + col_lo] = packh2(__floats2half2_rn(lo0, lo1));
                    *(uint32_t*)&dst[(size_t)(row0 + 8) * DM + col_hi] = packh2(__floats2half2_rn(hi0, hi1));
                }
            }
        }
    }
}

// ---------------- proj GEMM: BM=64, BN=128 -> 512 CTAs (R15 form) ----------
#define PSTG (192 * SKB)           // A(64 rows) + B(128 rows): 27648
#define PROJ_SMEM (2 * PSTG)       // 55296 -> 4 CTAs/SM capacity

__device__ __forceinline__ void proj_issue(int t, uint32_t st,
                                           const char* A, const char* B) {
#pragma unroll
    for (int i = 0; i < 4; i++) {
        int idx = t + i * 128;             // 0..511: A, 64 rows
        int row = idx >> 3, ch = idx & 7;
        cp_async16(st + row * SKB + ch * 16, A + (size_t)row * (DM * 2) + ch * 16);
    }
#pragma unroll
    for (int i = 0; i < 8; i++) {
        int idx = t + i * 128;             // 0..1023: B, 128 rows
        int row = idx >> 3, ch = idx & 7;
        cp_async16(st + 64 * SKB + row * SKB + ch * 16,
                   B + (size_t)row * (DM * 2) + ch * 16);
    }
    CP_COMMIT();
}

__global__ __launch_bounds__(128)
void proj_kernel(float* __restrict__ outp) {
    constexpr int NCH = 16;
    extern __shared__ char dsm[];
    const uint32_t sbase = smem_u32(dsm);
    const int t = threadIdx.x, lane = t & 31, wid = t >> 5;
    const int nt = blockIdx.x, mt = blockIdx.y;
    const int m0 = mt * 64, n0 = nt * 128;

    const char* pA = (const char*)g_a16h + (size_t)m0 * (DM * 2);
    const char* pB = (const char*)(g_w16o + (size_t)n0 * DM);

    float acc[2][8][4];
#pragma unroll
    for (int a = 0; a < 2; a++)
#pragma unroll
        for (int b = 0; b < 8; b++)
#pragma unroll
            for (int c = 0; c < 4; c++) acc[a][b][c] = 0.f;

#pragma unroll
    for (int c = 0; c < 2; c++)
        proj_issue(t, sbase + c * PSTG, pA + c * 128, pB + c * 128);

    const int wm = wid & 1, wn = wid >> 1;      // 2x2 warps, 32x64 each
    const int q = lane >> 3, r = lane & 7;

    for (int c = 0; c < NCH; c++) {
        if (c + 1 < NCH) { CP_WAIT1(); } else { CP_WAIT0(); }
        __syncthreads();

        const uint32_t sa = sbase + (c & 1) * PSTG + (wm * 32) * SKB;
        const uint32_t sb = sbase + (c & 1) * PSTG + 64 * SKB + (wn * 64) * SKB;
#pragma unroll
        for (int ks = 0; ks < 4; ks++) {
            uint32_t af[2][4], bf[4][4];
#pragma unroll
            for (int mb = 0; mb < 2; mb++)
                ldsm_x4(af[mb], sa + (mb * 16 + (q & 1) * 8 + r) * SKB
                                   + (ks * 16 + (q >> 1) * 8) * 2);
#pragma unroll
            for (int np = 0; np < 4; np++)
                ldsm_x4(bf[np], sb + (np * 16 + (q >> 1) * 8 + r) * SKB
                                   + (ks * 16 + (q & 1) * 8) * 2);
#pragma unroll
            for (int mb = 0; mb < 2; mb++)
#pragma unroll
                for (int np = 0; np < 4; np++) {
                    mma16816h(acc[mb][np * 2],     af[mb], &bf[np][0]);
                    mma16816h(acc[mb][np * 2 + 1], af[mb], &bf[np][2]);
                }
        }
        __syncthreads();
        if (c + 2 < NCH) {
            int cn = c + 2;
            proj_issue(t, sbase + (cn & 1) * PSTG, pA + cn * 128, pB + cn * 128);
        }
    }

    const int rr = lane >> 2, c2 = (lane & 3) * 2;
#pragma unroll
    for (int mb = 0; mb < 2; mb++) {
        int row0 = m0 + wm * 32 + mb * 16 + rr;
#pragma unroll
        for (int nb = 0; nb < 8; nb++) {
            int col = n0 + wn * 64 + nb * 8 + c2;
            *(float2*)&outp[(size_t)row0 * DM + col]       = make_float2(acc[mb][nb][0], acc[mb][nb][1]);
            *(float2*)&outp[(size_t)(row0 + 8) * DM + col] = make_float2(acc[mb][nb][2], acc[mb][nb][3]);
        }
    }
}

// ---------------- Flash attention: BM=64 (4 warps), 2-stage KV --------------
// CTA = (q-tile 64 rows, head). 128 thr / 4 warps; warp = 16 q-rows x full 64 kv.
// Per-warp instruction stream identical to the BM=128 version -> same numerics.
// 1024 CTAs, 4 CTAs/SM (46 KB smem, 16 warps/SM) -> finer load balance.
#define F_STG 9216             // Q tile: 64 rows x SKB
#define F_T   9216
#define F_STGSZ 18432
#define FLASH_SMEM (F_STG + 2 * F_STGSZ)   // 46080

__device__ __forceinline__ void flash_issue_kv(int t, uint32_t stg, int kbase, int h) {
    const size_t rowoff = (size_t)kbase * DM + h * 64;
    const __half* srcs[2] = {g_kh + rowoff, g_vh + rowoff};
#pragma unroll
    for (int i = 0; i < 8; i++) {
        int idx = t + i * 128;              // 0..1023
        int mat = idx >> 9;                 // 0..1
        int rem = idx & 511;
        int row = rem >> 3, ch = rem & 7;
        cp_async16(stg + mat * F_T + row * SKB + ch * 16,
                   (const char*)srcs[mat] + (size_t)row * (DM * 2) + ch * 16);
    }
    CP_COMMIT();
}

__global__ __launch_bounds__(128)
void flash_kernel() {
    extern __shared__ char dsm[];
    const uint32_t sbase = smem_u32(dsm);
    const int t = threadIdx.x, lane = t & 31, wid = t >> 5;
    const int h = blockIdx.y;
    const int qt = (int)gridDim.x - 1 - (int)blockIdx.x;   // heavy first
    const int qbase = qt * 64;
    const int ntiles = qt + 1;                              // kv tiles of 64

    // Q load (64 rows) + kv tile0 (one group), then kv tile1
    {
        const size_t rowoff = (size_t)qbase * DM + h * 64;
#pragma unroll
        for (int i = 0; i < 4; i++) {
            int idx = t + i * 128;           // 0..511 = 64 rows x 8 chunks
            int row = idx >> 3, ch = idx & 7;
            cp_async16(sbase + row * SKB + ch * 16,
                       (const char*)(g_qh + rowoff) + (size_t)row * (DM * 2) + ch * 16);
        }
        flash_issue_kv(t, sbase + F_STG, 0, h);            // commits Q + tile0
        flash_issue_kv(t, sbase + F_STG + F_STGSZ, 64, h); // tile 1 (may be unused; reads valid mem)
    }

    // Ones-column pad for both V stage buffers (bytes 128..143 of each V row;
    // cp.async only writes bytes 0..127, so this persists across stage reuse).
    {
        int buf = t >> 6, row = t & 63;      // 128 threads = 2 bufs x 64 rows
        uint32_t off = F_STG + buf * F_STGSZ + F_T + row * SKB + 128;
        *(uint4*)(dsm + off) = make_uint4(0x00003C00u, 0u, 0u, 0u);  // half {1,0,...,0}
    }

    CP_WAIT1();          // Q + tile0 ready
    __syncthreads();

    // preload Q fragments (persistent)
    const int q = lane >> 3, r = lane & 7;
    const int l16 = lane & 15;
    uint32_t qf[4][4];
#pragma unroll
    for (int ks = 0; ks < 4; ks++) {
        uint32_t ro = (wid * 16 + (q & 1) * 8 + r) * SKB + (ks * 16 + (q >> 1) * 8) * 2;
        ldsm_x4(qf[ks], sbase + ro);
    }
    // hoisted ones-column B fragment (identical for all tiles / k-steps)
    uint32_t bs_ones[2];
    ldsm_x2t(bs_ones, sbase + F_STG + F_T + l16 * SKB + 128);

    float o[8][4], o_sum[4];
#pragma unroll
    for (int a = 0; a < 8; a++)
#pragma unroll
        for (int b = 0; b < 4; b++) o[a][b] = 0.f;
#pragma unroll
    for (int b = 0; b < 4; b++) o_sum[b] = 0.f;
    float m0r = -1e30f, m1r = -1e30f;

    const int rr = lane >> 2, c2 = (lane & 3) * 2;
    const int qlo = qbase + wid * 16;
    const int qr0 = qlo + rr, qr1 = qr0 + 8;

    for (int kt = 0; kt < ntiles; kt++) {
        const uint32_t stg = sbase + F_STG + (kt & 1) * F_STGSZ;

        {   // all warps active: kt*64 <= qbase <= qlo+15 always holds here
            float s[8][4];
#pragma unroll
            for (int a = 0; a < 8; a++)
#pragma unroll
                for (int b = 0; b < 4; b++) s[a][b] = 0.f;

            // S = Q * K (logits in log2 domain; Q pre-scaled by log2e/8)
#pragma unroll
            for (int ks = 0; ks < 4; ks++) {
#pragma unroll
                for (int np = 0; np < 4; np++) {
                    uint32_t kf[4];
                    uint32_t ro = (np * 16 + (q >> 1) * 8 + r) * SKB + (ks * 16 + (q & 1) * 8) * 2;
                    ldsm_x4(kf, stg + 0 * F_T + ro);
                    mma16816h(s[np * 2],     qf[ks], &kf[0]);
                    mma16816h(s[np * 2 + 1], qf[ks], &kf[2]);
                }
            }

            // causal mask (diagonal-straddling tiles only)
            if (kt * 64 + 63 > qlo) {
#pragma unroll
                for (int nb = 0; nb < 8; nb++) {
                    int kc = kt * 64 + nb * 8 + c2;
                    if (kc     > qr0) s[nb][0] = -1e30f;
                    if (kc + 1 > qr0) s[nb][1] = -1e30f;
                    if (kc     > qr1) s[nb][2] = -1e30f;
                    if (kc + 1 > qr1) s[nb][3] = -1e30f;
                }
            }

            // online max (log2 domain)
            float mx0 = -1e30f, mx1 = -1e30f;
#pragma unroll
            for (int nb = 0; nb < 8; nb++) {
                mx0 = fmaxf(mx0, fmaxf(s[nb][0], s[nb][1]));
                mx1 = fmaxf(mx1, fmaxf(s[nb][2], s[nb][3]));
            }
            mx0 = fmaxf(mx0, __shfl_xor_sync(0xffffffffu, mx0, 1));
            mx0 = fmaxf(mx0, __shfl_xor_sync(0xffffffffu, mx0, 2));
            mx1 = fmaxf(mx1, __shfl_xor_sync(0xffffffffu, mx1, 1));
            mx1 = fmaxf(mx1, __shfl_xor_sync(0xffffffffu, mx1, 2));
            float mn0 = fmaxf(m0r, mx0), mn1 = fmaxf(m1r, mx1);
            float al0 = exp2f(m0r - mn0), al1 = exp2f(m1r - mn1);
            m0r = mn0;  m1r = mn1;
#pragma unroll
            for (int nb = 0; nb < 8; nb++) {
                o[nb][0] *= al0; o[nb][1] *= al0;
                o[nb][2] *= al1; o[nb][3] *= al1;
            }
            o_sum[0] *= al0; o_sum[1] *= al0;
            o_sum[2] *= al1; o_sum[3] *= al1;

            // P = exp2(s - m) computed in fp16x2; PV (+ ones-column row sum)
#pragma unroll
            for (int ks = 0; ks < 4; ks++) {
                uint32_t ph[4];
#pragma unroll
                for (int hf = 0; hf < 2; hf++) {
                    int nb = 2 * ks + hf;
                    __half2 e0 = h2exp2(__floats2half2_rn(s[nb][0] - mn0, s[nb][1] - mn0));
                    __half2 e1 = h2exp2(__floats2half2_rn(s[nb][2] - mn1, s[nb][3] - mn1));
                    ph[hf * 2]     = packh2(e0);
                    ph[hf * 2 + 1] = packh2(e1);
                }
#pragma unroll
                for (int dp = 0; dp < 4; dp++) {
                    uint32_t vf[4];
                    uint32_t ro = (ks * 16 + (q & 1) * 8 + r) * SKB + (dp * 16 + (q >> 1) * 8) * 2;
                    ldsm_x4t(vf, stg + 1 * F_T + ro);
                    mma16816h(o[dp * 2],     ph, &vf[0]);
                    mma16816h(o[dp * 2 + 1], ph, &vf[2]);
                }
                mma16816h(o_sum, ph, bs_ones);
            }
        }

        __syncthreads();          // done reading this stage
        if (kt + 2 < ntiles)
            flash_issue_kv(t, sbase + F_STG + (kt & 1) * F_STGSZ, (kt + 2) * 64, h);
        if (kt + 1 < ntiles) {
            if (kt + 2 < ntiles) { CP_WAIT1(); } else { CP_WAIT0(); }
            __syncthreads();      // tile kt+1 data visible to all
        }
    }

    // epilogue: l lives in o_sum col 0 (lanes with lane&3==0); broadcast in quad
    float l0 = __shfl_sync(0xffffffffu, o_sum[0], lane & 0x1C);
    float l1 = __shfl_sync(0xffffffffu, o_sum[2], lane & 0x1C);
    float inv0 = 1.f / l0, inv1 = 1.f / l1;
#pragma unroll
    for (int nb = 0; nb < 8; nb++) {
        int col = h * 64 + nb * 8 + c2;
        *(uint32_t*)&g_a16h[(size_t)qr0 * DM + col] =
            packh2(__floats2half2_rn(o[nb][0] * inv0, o[nb][1] * inv0));
        *(uint32_t*)&g_a16h[(size_t)qr1 * DM + col] =
            packh2(__floats2half2_rn(o[nb][2] * inv1, o[nb][3] * inv1));
    }
}

// ---------------- launch ----------------
extern "C" void kernel_launch(void* const* d_in, const int* in_sizes, int n_in,
                              void* d_out, int out_size) {
    const float* x  = (const float*)d_in[0];
    const float* Wq = (const float*)d_in[1];
    const float* Wk = (const float*)d_in[2];
    const float* Wv = (const float*)d_in[3];
    const float* Wo = (const float*)d_in[4];
    float* out = (float*)d_out;

    cudaFuncSetAttribute(qkv_gemm_kernel, cudaFuncAttributeMaxDynamicSharedMemorySize, GEMM_SMEM);
    cudaFuncSetAttribute(proj_kernel,     cudaFuncAttributeMaxDynamicSharedMemorySize, PROJ_SMEM);
    cudaFuncSetAttribute(flash_kernel,    cudaFuncAttributeMaxDynamicSharedMemorySize, FLASH_SMEM);

    rope_parts_kernel<<<20, 256>>>();
    cvt_all_kernel<<<8704, 256>>>(x, Wq, Wk, Wv, Wo);

    qkv_gemm_kernel<<<dim3(3 * DM / 128, SEQ / 128), 128, GEMM_SMEM>>>();

    flash_kernel<<<dim3(SEQ / 64, NH), 128, FLASH_SMEM>>>();

    proj_kernel<<<dim3(DM / 128, SEQ / 64), 128, PROJ_SMEM>>>(out);
}